// round 11
// baseline (speedup 1.0000x reference)
#include <cuda_runtime.h>
#include <math.h>

#define D 2048
#define SQ 2048
#define NB 8
#define NH 16
#define NL 2
#define DC 4096
#define IM 16384
#define PADID 50257
#define EPSLN 1e-5f
#define NLB (NL*NB)

typedef unsigned long long u64;
__device__ __forceinline__ u64 pk2(float x,float y){u64 r;asm("mov.b64 %0,{%1,%2};":"=l"(r):"f"(x),"f"(y));return r;}
__device__ __forceinline__ void fma2(u64&d,u64 a,u64 b){asm("fma.rn.f32x2 %0,%1,%2,%0;":"+l"(d):"l"(a),"l"(b));}
__device__ __forceinline__ void add2(u64&d,u64 a){asm("add.rn.f32x2 %0,%1,%0;":"+l"(d):"l"(a));}
__device__ __forceinline__ float2 up2(u64 v){float2 r;asm("mov.b64 {%0,%1},%2;":"=f"(r.x),"=f"(r.y):"l"(v));return r;}

__device__ float g_qp[16*NL*NB*D];
__device__ float g_q[NL*NB*D];
__device__ float g_r[NL*NB*D*NH];
__device__ float g_rt[NLB*NH*D];
__device__ float g_dgp[8*NLB*NH*SQ];
__device__ float g_sump[8*NLB*SQ];
__device__ float g_ssqp[8*NLB*SQ];
__device__ float g_wt[NLB*NH*SQ];
__device__ float g_W0[NLB*NH];
__device__ float g_cp[8*NLB*NH*D];
__device__ float g_ofp[8*NLB*D];
__device__ float g_aop[16*NLB*D];
__device__ float g_hcat[NB*DC];
__device__ float g_z1p[16*NB*IM];
__device__ float g_z1[NB*IM];
__device__ float g_m2p[64*NB*DC];
__device__ float g_hfin[NB*DC];

#define FMA8(A,W,Q0,Q1) do{ float _w=(W); \
  A[0]+=Q0.x*_w;A[1]+=Q0.y*_w;A[2]+=Q0.z*_w;A[3]+=Q0.w*_w; \
  A[4]+=Q1.x*_w;A[5]+=Q1.y*_w;A[6]+=Q1.z*_w;A[7]+=Q1.w*_w; }while(0)

// ---------- fused: idx scan + layernorm(last row) + q GEMV partial ----------
__global__ void __launch_bounds__(256) k_q(const float* __restrict__ Wq,
                    const int* __restrict__ ids,
                    const float* __restrict__ hs0,const float* __restrict__ hs1,
                    const float* __restrict__ lng,const float* __restrict__ lnb){
  int t=threadIdx.x, n=blockIdx.x*256+t, sp=blockIdx.y, l=blockIdx.z;
  int w=t>>5, lane=t&31;
  __shared__ float sln[128*NB];
  const float* hs=l?hs1:hs0;
  int best=-1;
  for(int s=lane;s<SQ;s+=32) if(ids[w*SQ+s]!=PADID) best=s;
  for(int o=16;o;o>>=1) best=max(best,__shfl_down_sync(~0u,best,o));
  best=__shfl_sync(~0u,best,0); if(best<0)best=0;
  const float* row=hs+((size_t)w*SQ+best)*D;
  float s1=0.f,s2=0.f;
  for(int i=lane;i<D;i+=32){ float v=row[i]; s1+=v; s2+=v*v; }
  for(int o=16;o;o>>=1){ s1+=__shfl_down_sync(~0u,s1,o); s2+=__shfl_down_sync(~0u,s2,o); }
  s1=__shfl_sync(~0u,s1,0); s2=__shfl_sync(~0u,s2,0);
  float m=s1*(1.f/D), rs=rsqrtf(s2*(1.f/D)-m*m+EPSLN);
  for(int i=lane;i<128;i+=32){
    int gi=sp*128+i;
    sln[i*8+w]=(row[gi]-m)*rs*lng[l*D+gi]+lnb[l*D+gi];
  }
  __syncthreads();
  const float* W=Wq+(size_t)l*D*D+(size_t)sp*128*D+n;
  float acc[NB]={0};
#pragma unroll 8
  for(int i=0;i<128;i++){
    float wv=W[(size_t)i*D];
    float4 l0=*(const float4*)&sln[i*8], l1=*(const float4*)&sln[i*8+4];
    FMA8(acc,wv,l0,l1);
  }
#pragma unroll
  for(int b=0;b<NB;b++) g_qp[(size_t)((sp*NL+l)*NB+b)*D+n]=acc[b];
}
__global__ void k_qred(){
  int idx=blockIdx.x*256+threadIdx.x; if(idx>=NL*NB*D) return;
  float s=0;
#pragma unroll
  for(int sp=0;sp<16;sp++) s+=g_qp[(size_t)sp*NL*NB*D+idx];
  g_q[idx]=s;
}

// ---------- r: tiled smem, no shuffles; writes both layouts ----------
__global__ void __launch_bounds__(256) k_r(const float* __restrict__ Wk){
  __shared__ __align__(16) float wk[64][132];
  __shared__ __align__(16) float qs[8][132];
  int t=threadIdx.x, chunk=blockIdx.x, h=blockIdx.y, l=blockIdx.z;
  int i0=chunk*64;
  for(int idx=t;idx<1024;idx+=256){ int b=idx>>7, d=idx&127; qs[b][d]=g_q[(l*NB+b)*D+h*128+d]; }
  const float* Wp=Wk+(size_t)l*D*D+(size_t)i0*D+h*128;
#pragma unroll
  for(int j=0;j<8;j++){
    int idx=t+j*256; int row=idx>>5, dq=idx&31;
    float4 v=*(const float4*)&Wp[(size_t)row*D+dq*4];
    *(float4*)&wk[row][dq*4]=v;
  }
  __syncthreads();
  int il=t>>3, b=t&7;
  float acc0=0.f, acc1=0.f;
#pragma unroll 8
  for(int dq=0;dq<32;dq++){
    float4 qv=*(const float4*)&qs[b][dq*4];
    float4 w0=*(const float4*)&wk[il][dq*4];
    float4 w1=*(const float4*)&wk[il+32][dq*4];
    acc0+=w0.x*qv.x+w0.y*qv.y+w0.z*qv.z+w0.w*qv.w;
    acc1+=w1.x*qv.x+w1.y*qv.y+w1.z*qv.z+w1.w*qv.w;
  }
  int lb=l*NB+b;
  g_r[((size_t)lb*D+i0+il)*NH+h]=acc0;
  g_r[((size_t)lb*D+i0+il+32)*NH+h]=acc1;
  g_rt[(size_t)(lb*NH+h)*D+i0+il]=acc0;
  g_rt[(size_t)(lb*NH+h)*D+i0+il+32]=acc1;
}

// ---------- pass1: 4 rows/thread, double-buffered x loads ----------
__global__ void __launch_bounds__(256) k_pass1(const float* __restrict__ hs0,const float* __restrict__ hs1,
                        const float* __restrict__ lng){
  __shared__ float rs[256*16];
  int t=threadIdx.x, sp=blockIdx.x, rg=blockIdx.y, lb=blockIdx.z;
  int l=lb>>3, b=lb&7, kb=sp*256;
  const float* x=(l?hs1:hs0)+(size_t)b*SQ*D;
  const float4* rsrc=(const float4*)(g_r+((size_t)lb*D+kb)*NH);
  float4* rs4=(float4*)rs;
  for(int idx=t;idx<1024;idx+=256){
    float g=lng[l*D+kb+(idx>>2)];
    float4 v=rsrc[idx]; v.x*=g; v.y*=g; v.z*=g; v.w*=g; rs4[idx]=v;
  }
  __syncthreads();
  int r0=rg*1024+t;
  const float4* xp0=(const float4*)(x+(size_t)(r0      )*D+kb);
  const float4* xp1=(const float4*)(x+(size_t)(r0+256  )*D+kb);
  const float4* xp2=(const float4*)(x+(size_t)(r0+512  )*D+kb);
  const float4* xp3=(const float4*)(x+(size_t)(r0+768  )*D+kb);
  u64 acc[4][8]={}; u64 s01=0,s23=0,q01=0,q23=0;
  float4 c0=xp0[0], c1=xp1[0], c2=xp2[0], c3=xp3[0];
  for(int kk=0;kk<256;kk+=4){
    int nidx=(kk>>2)+1; if(nidx>63) nidx=63;
    float4 n0=xp0[nidx], n1=xp1[nidx], n2=xp2[nidx], n3=xp3[nidx];
    float u0[4]={c0.x,c0.y,c0.z,c0.w};
    float u1[4]={c1.x,c1.y,c1.z,c1.w};
    float u2[4]={c2.x,c2.y,c2.z,c2.w};
    float u3[4]={c3.x,c3.y,c3.z,c3.w};
#pragma unroll
    for(int j=0;j<4;j++){
      float a=u0[j],bv=u1[j],c=u2[j],d=u3[j];
      u64 uv01=pk2(a,bv), uv23=pk2(c,d);
      add2(s01,uv01); fma2(q01,uv01,uv01);
      add2(s23,uv23); fma2(q23,uv23,uv23);
      u64 aa=pk2(a,a), bb=pk2(bv,bv), cc=pk2(c,c), dd=pk2(d,d);
      const ulonglong2* qp=(const ulonglong2*)(rs+(kk+j)*16);
      ulonglong2 qA=qp[0],qB=qp[1],qC=qp[2],qD=qp[3];
      fma2(acc[0][0],aa,qA.x); fma2(acc[0][1],aa,qA.y);
      fma2(acc[0][2],aa,qB.x); fma2(acc[0][3],aa,qB.y);
      fma2(acc[0][4],aa,qC.x); fma2(acc[0][5],aa,qC.y);
      fma2(acc[0][6],aa,qD.x); fma2(acc[0][7],aa,qD.y);
      fma2(acc[1][0],bb,qA.x); fma2(acc[1][1],bb,qA.y);
      fma2(acc[1][2],bb,qB.x); fma2(acc[1][3],bb,qB.y);
      fma2(acc[1][4],bb,qC.x); fma2(acc[1][5],bb,qC.y);
      fma2(acc[1][6],bb,qD.x); fma2(acc[1][7],bb,qD.y);
      fma2(acc[2][0],cc,qA.x); fma2(acc[2][1],cc,qA.y);
      fma2(acc[2][2],cc,qB.x); fma2(acc[2][3],cc,qB.y);
      fma2(acc[2][4],cc,qC.x); fma2(acc[2][5],cc,qC.y);
      fma2(acc[2][6],cc,qD.x); fma2(acc[2][7],cc,qD.y);
      fma2(acc[3][0],dd,qA.x); fma2(acc[3][1],dd,qA.y);
      fma2(acc[3][2],dd,qB.x); fma2(acc[3][3],dd,qB.y);
      fma2(acc[3][4],dd,qC.x); fma2(acc[3][5],dd,qC.y);
      fma2(acc[3][6],dd,qD.x); fma2(acc[3][7],dd,qD.y);
    }
    c0=n0; c1=n1; c2=n2; c3=n3;
  }
  size_t base=(size_t)((sp*NLB+lb)*NH)*SQ;
#pragma unroll
  for(int rr=0;rr<4;rr++){
    int row=r0+rr*256;
#pragma unroll
    for(int k=0;k<8;k++){
      float2 f=up2(acc[rr][k]);
      g_dgp[base+(size_t)(2*k)*SQ+row]=f.x;
      g_dgp[base+(size_t)(2*k+1)*SQ+row]=f.y;
    }
  }
  float2 s0=up2(s01), s1v=up2(s23), qq0=up2(q01), qq1=up2(q23);
  g_sump[(sp*NLB+lb)*SQ+r0]=s0.x;     g_sump[(sp*NLB+lb)*SQ+r0+256]=s0.y;
  g_sump[(sp*NLB+lb)*SQ+r0+512]=s1v.x; g_sump[(sp*NLB+lb)*SQ+r0+768]=s1v.y;
  g_ssqp[(sp*NLB+lb)*SQ+r0]=qq0.x;     g_ssqp[(sp*NLB+lb)*SQ+r0+256]=qq0.y;
  g_ssqp[(sp*NLB+lb)*SQ+r0+512]=qq1.x; g_ssqp[(sp*NLB+lb)*SQ+r0+768]=qq1.y;
}

// ---------- scores + softmax (t1/t2 inline, coalesced via g_rt) ----------
__global__ void k_soft(const float* __restrict__ lng,const float* __restrict__ lnb){
  int h=blockIdx.x, lb=blockIdx.y, t=threadIdx.x, l=lb>>3;
  __shared__ float sm[256];
  __shared__ float t1s,t2s;
  const float* rt=g_rt+(size_t)(lb*NH+h)*D;
  float p1=0.f,p2=0.f;
#pragma unroll
  for(int k=0;k<8;k++){
    int i=t+k*256;
    float rv=rt[i];
    p1+=lng[l*D+i]*rv; p2+=lnb[l*D+i]*rv;
  }
  sm[t]=p1; __syncthreads();
  for(int o=128;o;o>>=1){ if(t<o) sm[t]+=sm[t+o]; __syncthreads(); }
  if(t==0) t1s=sm[0]; __syncthreads();
  sm[t]=p2; __syncthreads();
  for(int o=128;o;o>>=1){ if(t<o) sm[t]+=sm[t+o]; __syncthreads(); }
  if(t==0) t2s=sm[0]; __syncthreads();
  float t1=t1s, t2=t2s;
  float sc[8],mm[8],rr[8];
#pragma unroll
  for(int k=0;k<8;k++){
    int s=t+k*256; float su=0,sq=0,dg=0;
#pragma unroll
    for(int sp=0;sp<8;sp++){
      su+=g_sump[(sp*NLB+lb)*SQ+s]; sq+=g_ssqp[(sp*NLB+lb)*SQ+s];
      dg+=g_dgp[(size_t)((sp*NLB+lb)*NH+h)*SQ+s];
    }
    float m=su*(1.f/D), var=sq*(1.f/D)-m*m, rsd=rsqrtf(var+EPSLN);
    mm[k]=m; rr[k]=rsd; sc[k]=rsd*(dg-m*t1)+t2;
  }
  float mx=sc[0];
#pragma unroll
  for(int k=1;k<8;k++) mx=fmaxf(mx,sc[k]);
  sm[t]=mx; __syncthreads();
  for(int o=128;o;o>>=1){ if(t<o) sm[t]=fmaxf(sm[t],sm[t+o]); __syncthreads(); }
  mx=sm[0]; __syncthreads();
  float e[8],es=0;
#pragma unroll
  for(int k=0;k<8;k++){ e[k]=expf(sc[k]-mx); es+=e[k]; }
  sm[t]=es; __syncthreads();
  for(int o=128;o;o>>=1){ if(t<o) sm[t]+=sm[t+o]; __syncthreads(); }
  float inv=1.f/sm[0]; __syncthreads();
  float w0=0;
#pragma unroll
  for(int k=0;k<8;k++){
    float wt=e[k]*inv*rr[k];
    g_wt[(size_t)(lb*NH+h)*SQ+t+k*256]=wt; w0+=wt*mm[k];
  }
  sm[t]=w0; __syncthreads();
  for(int o=128;o;o>>=1){ if(t<o) sm[t]+=sm[t+o]; __syncthreads(); }
  if(t==0) g_W0[lb*NH+h]=sm[0];
}

// ---------- pass2: 4 cols/thread, double-buffered x loads ----------
__global__ void __launch_bounds__(256) k_pass2(const float* __restrict__ hs0,const float* __restrict__ hs1){
  __shared__ float swt[256*16];
  int t=threadIdx.x, sp=blockIdx.x, cg=blockIdx.y, lb=blockIdx.z;
  int l=lb>>3, b=lb&7, sb=sp*256;
#pragma unroll
  for(int h=0;h<16;h++)
    swt[t*16+h]=g_wt[(size_t)(lb*NH+h)*SQ+sb+t];
  __syncthreads();
  const float* x=(l?hs1:hs0)+(size_t)b*SQ*D;
  int c=cg*1024+t*4;
  u64 acc[4][8]={};
  float4 cv[4];
#pragma unroll
  for(int j=0;j<4;j++) cv[j]=*(const float4*)&x[(size_t)(sb+j)*D+c];
  for(int s=0;s<256;s+=4){
    int ns=s+4; if(ns>252) ns=252;
    float4 nv[4];
#pragma unroll
    for(int j=0;j<4;j++) nv[j]=*(const float4*)&x[(size_t)(sb+ns+j)*D+c];
#pragma unroll
    for(int j=0;j<4;j++){
      u64 aa=pk2(cv[j].x,cv[j].x), bb=pk2(cv[j].y,cv[j].y);
      u64 cc=pk2(cv[j].z,cv[j].z), dd=pk2(cv[j].w,cv[j].w);
      const ulonglong2* qp=(const ulonglong2*)(swt+(s+j)*16);
      ulonglong2 qA=qp[0],qB=qp[1],qC=qp[2],qD=qp[3];
      fma2(acc[0][0],aa,qA.x); fma2(acc[0][1],aa,qA.y);
      fma2(acc[0][2],aa,qB.x); fma2(acc[0][3],aa,qB.y);
      fma2(acc[0][4],aa,qC.x); fma2(acc[0][5],aa,qC.y);
      fma2(acc[0][6],aa,qD.x); fma2(acc[0][7],aa,qD.y);
      fma2(acc[1][0],bb,qA.x); fma2(acc[1][1],bb,qA.y);
      fma2(acc[1][2],bb,qB.x); fma2(acc[1][3],bb,qB.y);
      fma2(acc[1][4],bb,qC.x); fma2(acc[1][5],bb,qC.y);
      fma2(acc[1][6],bb,qD.x); fma2(acc[1][7],bb,qD.y);
      fma2(acc[2][0],cc,qA.x); fma2(acc[2][1],cc,qA.y);
      fma2(acc[2][2],cc,qB.x); fma2(acc[2][3],cc,qB.y);
      fma2(acc[2][4],cc,qC.x); fma2(acc[2][5],cc,qC.y);
      fma2(acc[2][6],cc,qD.x); fma2(acc[2][7],cc,qD.y);
      fma2(acc[3][0],dd,qA.x); fma2(acc[3][1],dd,qA.y);
      fma2(acc[3][2],dd,qB.x); fma2(acc[3][3],dd,qB.y);
      fma2(acc[3][4],dd,qC.x); fma2(acc[3][5],dd,qC.y);
      fma2(acc[3][6],dd,qD.x); fma2(acc[3][7],dd,qD.y);
    }
#pragma unroll
    for(int j=0;j<4;j++) cv[j]=nv[j];
  }
  size_t base=(size_t)((sp*NLB+lb)*NH)*D;
#pragma unroll
  for(int k=0;k<8;k++){
    float2 f0=up2(acc[0][k]), f1=up2(acc[1][k]), f2=up2(acc[2][k]), f3=up2(acc[3][k]);
    float4 stA; stA.x=f0.x; stA.y=f1.x; stA.z=f2.x; stA.w=f3.x;
    float4 stB; stB.x=f0.y; stB.y=f1.y; stB.z=f2.y; stB.w=f3.y;
    *(float4*)&g_cp[base+(size_t)(2*k)*D+c]=stA;
    *(float4*)&g_cp[base+(size_t)(2*k+1)*D+c]=stB;
  }
}

// ---------- oflat = c @ Wv  (cred fused into smem build) ----------
__global__ void k_of(const float* __restrict__ Wv,
                     const float* __restrict__ lng,const float* __restrict__ lnb){
  __shared__ float sc[256*8];
  int t=threadIdx.x, h=blockIdx.x, sp=blockIdx.y, l=blockIdx.z, db=sp*256;
  for(int idx=t;idx<256*8;idx+=128){
    int d=idx>>3, b=idx&7, lb=l*8+b;
    float s=0;
#pragma unroll
    for(int p=0;p<8;p++) s+=g_cp[(size_t)((p*NLB+lb)*NH+h)*D+db+d];
    sc[idx]=lng[l*D+db+d]*(s-g_W0[lb*NH+h])+lnb[l*D+db+d];
  }
  __syncthreads();
  const float* W=Wv+(size_t)l*D*D+(size_t)db*D+h*128+t;
  float acc[NB]={0};
#pragma unroll 8
  for(int d=0;d<256;d++){
    float w=W[(size_t)d*D];
    float4 c0=*(const float4*)&sc[d*8],c1=*(const float4*)&sc[d*8+4];
    FMA8(acc,w,c0,c1);
  }
#pragma unroll
  for(int b=0;b<NB;b++) g_ofp[(size_t)((sp*NL+l)*NB+b)*D+h*128+t]=acc[b];
}

// ---------- attnout = of @ Wo -> hcat partials ----------
__global__ void k_ao(const float* __restrict__ Wo){
  __shared__ float sof[128*8];
  int t=threadIdx.x, cb=blockIdx.x, sp=blockIdx.y, l=blockIdx.z, mb=sp*128, n=cb*256+t;
  for(int idx=t;idx<128*8;idx+=256){
    int m=idx>>3, b=idx&7;
    float s=0;
#pragma unroll
    for(int p=0;p<8;p++) s+=g_ofp[(size_t)((p*NL+l)*NB+b)*D+mb+m];
    sof[idx]=s;
  }
  __syncthreads();
  const float* W=Wo+(size_t)l*D*D+(size_t)mb*D+n;
  float acc[NB]={0};
#pragma unroll 8
  for(int m=0;m<128;m++){
    float w=W[(size_t)m*D];
    float4 o0=*(const float4*)&sof[m*8],o1=*(const float4*)&sof[m*8+4];
    FMA8(acc,w,o0,o1);
  }
#pragma unroll
  for(int b=0;b<NB;b++) g_aop[(size_t)((sp*NL+l)*NB+b)*D+n]=acc[b];
}
__global__ void k_aored(const float* __restrict__ bo){
  int idx=blockIdx.x*256+threadIdx.x; if(idx>=NLB*D) return;
  int n=idx&(D-1), lb=idx>>11, l=lb>>3, b=lb&7;
  float s=0;
#pragma unroll
  for(int sp=0;sp<16;sp++) s+=g_aop[(size_t)sp*NLB*D+idx];
  g_hcat[b*DC+l*D+n]=s+bo[l*D+n];
}

// ---------- MLP layer 1 (f32x2 packed, double-buffered weights) ----------
__global__ void k_m1(const float* __restrict__ W1){
  __shared__ float sh[256*8];
  int t=threadIdx.x, p=blockIdx.x*1024+t*4, cb=blockIdx.y*256;
  for(int idx=t;idx<256*8;idx+=256){ int c=idx>>3,b=idx&7; sh[idx]=g_hcat[b*DC+cb+c]; }
  __syncthreads();
  const float* W=W1+(size_t)cb*IM+p;
  u64 accA[8]={},accB[8]={};
  ulonglong2 wc=*(const ulonglong2*)W;
#pragma unroll 4
  for(int c=0;c<256;c++){
    int nc=c+1; if(nc>255) nc=255;
    ulonglong2 wn=*(const ulonglong2*)&W[(size_t)nc*IM];
    float4 h0=*(const float4*)&sh[c*8], h1=*(const float4*)&sh[c*8+4];
    float hb[8]={h0.x,h0.y,h0.z,h0.w,h1.x,h1.y,h1.z,h1.w};
#pragma unroll
    for(int b=0;b<8;b++){
      u64 hh=pk2(hb[b],hb[b]);
      fma2(accA[b],hh,wc.x); fma2(accB[b],hh,wc.y);
    }
    wc=wn;
  }
#pragma unroll
  for(int b=0;b<8;b++){
    float2 fa=up2(accA[b]), fb=up2(accB[b]);
    float4 st; st.x=fa.x; st.y=fa.y; st.z=fb.x; st.w=fb.y;
    *(float4*)&g_z1p[(size_t)(blockIdx.y*NB+b)*IM+p]=st;
  }
}
__global__ void k_z1red(const float* __restrict__ b1){
  int idx=blockIdx.x*256+threadIdx.x; if(idx>=NB*IM) return;
  int p=idx&(IM-1);
  float s=b1[p];
#pragma unroll
  for(int sp=0;sp<16;sp++) s+=g_z1p[(size_t)sp*NB*IM+idx];
  g_z1[idx]=0.5f*s*(1.0f+erff(s*0.70710678118654752f));
}

// ---------- MLP layer 2 (f32x2 packed, double-buffered weights) ----------
__global__ void k_m2(const float* __restrict__ W2){
  __shared__ float sz[256*8];
  int t=threadIdx.x, c=blockIdx.x*1024+t*4, pb=blockIdx.y*256;
  for(int idx=t;idx<256*8;idx+=256){ int pp=idx>>3,b=idx&7; sz[idx]=g_z1[b*IM+pb+pp]; }
  __syncthreads();
  const float* W=W2+(size_t)pb*DC+c;
  u64 accA[8]={},accB[8]={};
  ulonglong2 wc=*(const ulonglong2*)W;
#pragma unroll 4
  for(int pp=0;pp<256;pp++){
    int np=pp+1; if(np>255) np=255;
    ulonglong2 wn=*(const ulonglong2*)&W[(size_t)np*DC];
    float4 z0=*(const float4*)&sz[pp*8], z1v=*(const float4*)&sz[pp*8+4];
    float zb[8]={z0.x,z0.y,z0.z,z0.w,z1v.x,z1v.y,z1v.z,z1v.w};
#pragma unroll
    for(int b=0;b<8;b++){
      u64 zz=pk2(zb[b],zb[b]);
      fma2(accA[b],zz,wc.x); fma2(accB[b],zz,wc.y);
    }
    wc=wn;
  }
#pragma unroll
  for(int b=0;b<8;b++){
    float2 fa=up2(accA[b]), fb=up2(accB[b]);
    float4 st; st.x=fa.x; st.y=fa.y; st.z=fb.x; st.w=fb.y;
    *(float4*)&g_m2p[(size_t)(blockIdx.y*NB+b)*DC+c]=st;
  }
}
__global__ void k_m2red(const float* __restrict__ b2){
  int idx=blockIdx.x*256+threadIdx.x; if(idx>=NB*DC) return;
  int c=idx&(DC-1);
  float s=b2[c];
#pragma unroll
  for(int sp=0;sp<64;sp++) s+=g_m2p[(size_t)sp*NB*DC+idx];
  g_hfin[idx]=g_hcat[idx]+s;
}

// ---------- final logits ----------
__global__ void k_out(const float* __restrict__ Wl,const float* __restrict__ bl,
                      float* __restrict__ out){
  int b=blockIdx.x, t=threadIdx.x;
  float a0=0,a1=0;
  for(int c=t;c<DC;c+=256){
    float h=g_hfin[b*DC+c];
    a0+=h*Wl[c*2]; a1+=h*Wl[c*2+1];
  }
  __shared__ float s0[256],s1[256];
  s0[t]=a0; s1[t]=a1; __syncthreads();
  for(int o=128;o;o>>=1){ if(t<o){ s0[t]+=s0[t+o]; s1[t]+=s1[t+o]; } __syncthreads(); }
  if(t==0){ out[b*2]=s0[0]+bl[0]; out[b*2+1]=s1[0]+bl[1]; }
}

extern "C" void kernel_launch(void* const* d_in, const int* in_sizes, int n_in,
                              void* d_out, int out_size){
  const float* hs0=(const float*)d_in[0];
  const float* hs1=(const float*)d_in[1];
  const int*   ids=(const int*)d_in[2];
  const float* lng=(const float*)d_in[3];
  const float* lnb=(const float*)d_in[4];
  const float* Wq =(const float*)d_in[5];
  const float* Wk =(const float*)d_in[6];
  const float* Wv =(const float*)d_in[7];
  const float* Wo =(const float*)d_in[8];
  const float* bo =(const float*)d_in[9];
  const float* W1 =(const float*)d_in[10];
  const float* b1 =(const float*)d_in[11];
  const float* W2 =(const float*)d_in[12];
  const float* b2 =(const float*)d_in[13];
  const float* Wl =(const float*)d_in[14];
  const float* bl =(const float*)d_in[15];
  float* out=(float*)d_out;

  k_q<<<dim3(8,16,NL),256>>>(Wq,ids,hs0,hs1,lng,lnb);
  k_qred<<<(NL*NB*D)/256,256>>>();
  k_r<<<dim3(32,16,NL),256>>>(Wk);
  k_pass1<<<dim3(8,2,NLB),256>>>(hs0,hs1,lng);   // 4th launch: profiled
  k_soft<<<dim3(NH,NLB),256>>>(lng,lnb);
  k_pass2<<<dim3(8,2,NLB),256>>>(hs0,hs1);
  k_of<<<dim3(16,8,NL),128>>>(Wv,lng,lnb);
  k_ao<<<dim3(8,16,NL),256>>>(Wo);
  k_aored<<<(NLB*D)/256,256>>>(bo);
  k_m1<<<dim3(IM/1024,16),256>>>(W1);
  k_z1red<<<(NB*IM)/256,256>>>(b1);
  k_m2<<<dim3(DC/1024,64),256>>>(W2);
  k_m2red<<<(NB*DC)/256,256>>>(b2);
  k_out<<<NB,256>>>(Wl,bl,out);
}

// round 12
// speedup vs baseline: 1.0732x; 1.0732x over previous
#include <cuda_runtime.h>
#include <math.h>

#define D 2048
#define SQ 2048
#define NB 8
#define NH 16
#define NL 2
#define DC 4096
#define IM 16384
#define PADID 50257
#define EPSLN 1e-5f
#define NLB (NL*NB)

typedef unsigned long long u64;
__device__ __forceinline__ u64 pk2(float x,float y){u64 r;asm("mov.b64 %0,{%1,%2};":"=l"(r):"f"(x),"f"(y));return r;}
__device__ __forceinline__ void fma2(u64&d,u64 a,u64 b){asm("fma.rn.f32x2 %0,%1,%2,%0;":"+l"(d):"l"(a),"l"(b));}
__device__ __forceinline__ void add2(u64&d,u64 a){asm("add.rn.f32x2 %0,%1,%0;":"+l"(d):"l"(a));}
__device__ __forceinline__ float2 up2(u64 v){float2 r;asm("mov.b64 {%0,%1},%2;":"=f"(r.x),"=f"(r.y):"l"(v));return r;}

__device__ float g_qp[16*NL*NB*D];
__device__ float g_q[NL*NB*D];
__device__ float g_r[NL*NB*D*NH];
__device__ float g_rt[NLB*NH*D];
__device__ float g_dgp[8*NLB*NH*SQ];
__device__ float g_sump[8*NLB*SQ];
__device__ float g_ssqp[8*NLB*SQ];
__device__ float g_wt[NLB*NH*SQ];
__device__ float g_W0[NLB*NH];
__device__ float g_cp[8*NLB*NH*D];
__device__ float g_ofp[8*NLB*D];
__device__ float g_aop[16*NLB*D];
__device__ float g_hcat[NB*DC];
__device__ float g_z1p[16*NB*IM];
__device__ float g_z1[NB*IM];
__device__ float g_m2p[64*NB*DC];
__device__ float g_hfin[NB*DC];

#define FMA8(A,W,Q0,Q1) do{ float _w=(W); \
  A[0]+=Q0.x*_w;A[1]+=Q0.y*_w;A[2]+=Q0.z*_w;A[3]+=Q0.w*_w; \
  A[4]+=Q1.x*_w;A[5]+=Q1.y*_w;A[6]+=Q1.z*_w;A[7]+=Q1.w*_w; }while(0)

// ---------- fused: idx scan + layernorm(last row) + q GEMV partial ----------
__global__ void __launch_bounds__(256) k_q(const float* __restrict__ Wq,
                    const int* __restrict__ ids,
                    const float* __restrict__ hs0,const float* __restrict__ hs1,
                    const float* __restrict__ lng,const float* __restrict__ lnb){
  int t=threadIdx.x, n=blockIdx.x*256+t, sp=blockIdx.y, l=blockIdx.z;
  int w=t>>5, lane=t&31;
  __shared__ float sln[128*NB];
  const float* hs=l?hs1:hs0;
  int best=-1;
  for(int s=lane;s<SQ;s+=32) if(ids[w*SQ+s]!=PADID) best=s;
  for(int o=16;o;o>>=1) best=max(best,__shfl_down_sync(~0u,best,o));
  best=__shfl_sync(~0u,best,0); if(best<0)best=0;
  const float* row=hs+((size_t)w*SQ+best)*D;
  float s1=0.f,s2=0.f;
  for(int i=lane;i<D;i+=32){ float v=row[i]; s1+=v; s2+=v*v; }
  for(int o=16;o;o>>=1){ s1+=__shfl_down_sync(~0u,s1,o); s2+=__shfl_down_sync(~0u,s2,o); }
  s1=__shfl_sync(~0u,s1,0); s2=__shfl_sync(~0u,s2,0);
  float m=s1*(1.f/D), rs=rsqrtf(s2*(1.f/D)-m*m+EPSLN);
  for(int i=lane;i<128;i+=32){
    int gi=sp*128+i;
    sln[i*8+w]=(row[gi]-m)*rs*lng[l*D+gi]+lnb[l*D+gi];
  }
  __syncthreads();
  const float* W=Wq+(size_t)l*D*D+(size_t)sp*128*D+n;
  float acc[NB]={0};
#pragma unroll 8
  for(int i=0;i<128;i++){
    float wv=W[(size_t)i*D];
    float4 l0=*(const float4*)&sln[i*8], l1=*(const float4*)&sln[i*8+4];
    FMA8(acc,wv,l0,l1);
  }
#pragma unroll
  for(int b=0;b<NB;b++) g_qp[(size_t)((sp*NL+l)*NB+b)*D+n]=acc[b];
}
__global__ void k_qred(){
  int idx=blockIdx.x*256+threadIdx.x; if(idx>=NL*NB*D) return;
  float s=0;
#pragma unroll
  for(int sp=0;sp<16;sp++) s+=g_qp[(size_t)sp*NL*NB*D+idx];
  g_q[idx]=s;
}

// ---------- r: tiled smem, no shuffles; writes both layouts ----------
__global__ void __launch_bounds__(256) k_r(const float* __restrict__ Wk){
  __shared__ __align__(16) float wk[64][132];
  __shared__ __align__(16) float qs[8][132];
  int t=threadIdx.x, chunk=blockIdx.x, h=blockIdx.y, l=blockIdx.z;
  int i0=chunk*64;
  for(int idx=t;idx<1024;idx+=256){ int b=idx>>7, d=idx&127; qs[b][d]=g_q[(l*NB+b)*D+h*128+d]; }
  const float* Wp=Wk+(size_t)l*D*D+(size_t)i0*D+h*128;
#pragma unroll
  for(int j=0;j<8;j++){
    int idx=t+j*256; int row=idx>>5, dq=idx&31;
    float4 v=*(const float4*)&Wp[(size_t)row*D+dq*4];
    *(float4*)&wk[row][dq*4]=v;
  }
  __syncthreads();
  int il=t>>3, b=t&7;
  float acc0=0.f, acc1=0.f;
#pragma unroll 8
  for(int dq=0;dq<32;dq++){
    float4 qv=*(const float4*)&qs[b][dq*4];
    float4 w0=*(const float4*)&wk[il][dq*4];
    float4 w1=*(const float4*)&wk[il+32][dq*4];
    acc0+=w0.x*qv.x+w0.y*qv.y+w0.z*qv.z+w0.w*qv.w;
    acc1+=w1.x*qv.x+w1.y*qv.y+w1.z*qv.z+w1.w*qv.w;
  }
  int lb=l*NB+b;
  g_r[((size_t)lb*D+i0+il)*NH+h]=acc0;
  g_r[((size_t)lb*D+i0+il+32)*NH+h]=acc1;
  g_rt[(size_t)(lb*NH+h)*D+i0+il]=acc0;
  g_rt[(size_t)(lb*NH+h)*D+i0+il+32]=acc1;
}

// ---------- pass1: smem-staged x tiles (coalesced), 1 row/thread ----------
__global__ void __launch_bounds__(256) k_pass1(const float* __restrict__ hs0,const float* __restrict__ hs1,
                        const float* __restrict__ lng){
  __shared__ float rs[256*16];      // r*g operands for this k-split
  __shared__ float xt[256*20];      // 256-row x 16-k tile, stride 20 (conflict-free)
  int t=threadIdx.x, sp=blockIdx.x, rg=blockIdx.y, lb=blockIdx.z;
  int l=lb>>3, b=lb&7, kb=sp*256;
  const float* x=(l?hs1:hs0)+(size_t)b*SQ*D;
  const float4* rsrc=(const float4*)(g_r+((size_t)lb*D+kb)*NH);
  float4* rs4=(float4*)rs;
  for(int idx=t;idx<1024;idx+=256){
    float g=lng[l*D+kb+(idx>>2)];
    float4 v=rsrc[idx]; v.x*=g; v.y*=g; v.z*=g; v.w*=g; rs4[idx]=v;
  }
  int rowbase=rg*256;
  u64 acc[8]={}; float s1=0.f, ss=0.f;
  for(int ch=0;ch<16;ch++){
    int kk=ch*16;
    __syncthreads();
    // cooperative coalesced tile load: 4 lanes per row (64B/row)
#pragma unroll
    for(int p=0;p<4;p++){
      int idx=p*256+t; int rr=idx>>2, kq=idx&3;
      float4 v=*(const float4*)&x[(size_t)(rowbase+rr)*D+kb+kk+kq*4];
      *(float4*)&xt[rr*20+kq*4]=v;
    }
    __syncthreads();
#pragma unroll
    for(int jj=0;jj<4;jj++){
      float4 xv=*(const float4*)&xt[t*20+jj*4];
      float u4[4]={xv.x,xv.y,xv.z,xv.w};
#pragma unroll
      for(int e=0;e<4;e++){
        float u=u4[e];
        s1+=u; ss+=u*u;
        u64 uu=pk2(u,u);
        const ulonglong2* qp=(const ulonglong2*)(rs+(kk+jj*4+e)*16);
        ulonglong2 qA=qp[0],qB=qp[1],qC=qp[2],qD=qp[3];
        fma2(acc[0],uu,qA.x); fma2(acc[1],uu,qA.y);
        fma2(acc[2],uu,qB.x); fma2(acc[3],uu,qB.y);
        fma2(acc[4],uu,qC.x); fma2(acc[5],uu,qC.y);
        fma2(acc[6],uu,qD.x); fma2(acc[7],uu,qD.y);
      }
    }
  }
  int row=rowbase+t;
  size_t base=(size_t)((sp*NLB+lb)*NH)*SQ;
#pragma unroll
  for(int k=0;k<8;k++){
    float2 f=up2(acc[k]);
    g_dgp[base+(size_t)(2*k)*SQ+row]=f.x;
    g_dgp[base+(size_t)(2*k+1)*SQ+row]=f.y;
  }
  g_sump[(sp*NLB+lb)*SQ+row]=s1;
  g_ssqp[(sp*NLB+lb)*SQ+row]=ss;
}

// ---------- scores + softmax (t1/t2 inline, coalesced via g_rt) ----------
__global__ void k_soft(const float* __restrict__ lng,const float* __restrict__ lnb){
  int h=blockIdx.x, lb=blockIdx.y, t=threadIdx.x, l=lb>>3;
  __shared__ float sm[256];
  __shared__ float t1s,t2s;
  const float* rt=g_rt+(size_t)(lb*NH+h)*D;
  float p1=0.f,p2=0.f;
#pragma unroll
  for(int k=0;k<8;k++){
    int i=t+k*256;
    float rv=rt[i];
    p1+=lng[l*D+i]*rv; p2+=lnb[l*D+i]*rv;
  }
  sm[t]=p1; __syncthreads();
  for(int o=128;o;o>>=1){ if(t<o) sm[t]+=sm[t+o]; __syncthreads(); }
  if(t==0) t1s=sm[0]; __syncthreads();
  sm[t]=p2; __syncthreads();
  for(int o=128;o;o>>=1){ if(t<o) sm[t]+=sm[t+o]; __syncthreads(); }
  if(t==0) t2s=sm[0]; __syncthreads();
  float t1=t1s, t2=t2s;
  float sc[8],mm[8],rr[8];
#pragma unroll
  for(int k=0;k<8;k++){
    int s=t+k*256; float su=0,sq=0,dg=0;
#pragma unroll
    for(int sp=0;sp<8;sp++){
      su+=g_sump[(sp*NLB+lb)*SQ+s]; sq+=g_ssqp[(sp*NLB+lb)*SQ+s];
      dg+=g_dgp[(size_t)((sp*NLB+lb)*NH+h)*SQ+s];
    }
    float m=su*(1.f/D), var=sq*(1.f/D)-m*m, rsd=rsqrtf(var+EPSLN);
    mm[k]=m; rr[k]=rsd; sc[k]=rsd*(dg-m*t1)+t2;
  }
  float mx=sc[0];
#pragma unroll
  for(int k=1;k<8;k++) mx=fmaxf(mx,sc[k]);
  sm[t]=mx; __syncthreads();
  for(int o=128;o;o>>=1){ if(t<o) sm[t]=fmaxf(sm[t],sm[t+o]); __syncthreads(); }
  mx=sm[0]; __syncthreads();
  float e[8],es=0;
#pragma unroll
  for(int k=0;k<8;k++){ e[k]=expf(sc[k]-mx); es+=e[k]; }
  sm[t]=es; __syncthreads();
  for(int o=128;o;o>>=1){ if(t<o) sm[t]+=sm[t+o]; __syncthreads(); }
  float inv=1.f/sm[0]; __syncthreads();
  float w0=0;
#pragma unroll
  for(int k=0;k<8;k++){
    float wt=e[k]*inv*rr[k];
    g_wt[(size_t)(lb*NH+h)*SQ+t+k*256]=wt; w0+=wt*mm[k];
  }
  sm[t]=w0; __syncthreads();
  for(int o=128;o;o>>=1){ if(t<o) sm[t]+=sm[t+o]; __syncthreads(); }
  if(t==0) g_W0[lb*NH+h]=sm[0];
}

// ---------- pass2: 4 cols/thread (R10 form, already coalesced) ----------
__global__ void __launch_bounds__(256) k_pass2(const float* __restrict__ hs0,const float* __restrict__ hs1){
  __shared__ float swt[256*16];
  int t=threadIdx.x, sp=blockIdx.x, cg=blockIdx.y, lb=blockIdx.z;
  int l=lb>>3, b=lb&7, sb=sp*256;
#pragma unroll
  for(int h=0;h<16;h++)
    swt[t*16+h]=g_wt[(size_t)(lb*NH+h)*SQ+sb+t];
  __syncthreads();
  const float* x=(l?hs1:hs0)+(size_t)b*SQ*D;
  int c=cg*1024+t*4;
  u64 acc[4][8]={};
  for(int s=0;s<256;s+=4){
    float4 xv[4];
#pragma unroll
    for(int j=0;j<4;j++) xv[j]=*(const float4*)&x[(size_t)(sb+s+j)*D+c];
#pragma unroll
    for(int j=0;j<4;j++){
      u64 aa=pk2(xv[j].x,xv[j].x), bb=pk2(xv[j].y,xv[j].y);
      u64 cc=pk2(xv[j].z,xv[j].z), dd=pk2(xv[j].w,xv[j].w);
      const ulonglong2* qp=(const ulonglong2*)(swt+(s+j)*16);
      ulonglong2 qA=qp[0],qB=qp[1],qC=qp[2],qD=qp[3];
      fma2(acc[0][0],aa,qA.x); fma2(acc[0][1],aa,qA.y);
      fma2(acc[0][2],aa,qB.x); fma2(acc[0][3],aa,qB.y);
      fma2(acc[0][4],aa,qC.x); fma2(acc[0][5],aa,qC.y);
      fma2(acc[0][6],aa,qD.x); fma2(acc[0][7],aa,qD.y);
      fma2(acc[1][0],bb,qA.x); fma2(acc[1][1],bb,qA.y);
      fma2(acc[1][2],bb,qB.x); fma2(acc[1][3],bb,qB.y);
      fma2(acc[1][4],bb,qC.x); fma2(acc[1][5],bb,qC.y);
      fma2(acc[1][6],bb,qD.x); fma2(acc[1][7],bb,qD.y);
      fma2(acc[2][0],cc,qA.x); fma2(acc[2][1],cc,qA.y);
      fma2(acc[2][2],cc,qB.x); fma2(acc[2][3],cc,qB.y);
      fma2(acc[2][4],cc,qC.x); fma2(acc[2][5],cc,qC.y);
      fma2(acc[2][6],cc,qD.x); fma2(acc[2][7],cc,qD.y);
      fma2(acc[3][0],dd,qA.x); fma2(acc[3][1],dd,qA.y);
      fma2(acc[3][2],dd,qB.x); fma2(acc[3][3],dd,qB.y);
      fma2(acc[3][4],dd,qC.x); fma2(acc[3][5],dd,qC.y);
      fma2(acc[3][6],dd,qD.x); fma2(acc[3][7],dd,qD.y);
    }
  }
  size_t base=(size_t)((sp*NLB+lb)*NH)*D;
#pragma unroll
  for(int k=0;k<8;k++){
    float2 f0=up2(acc[0][k]), f1=up2(acc[1][k]), f2=up2(acc[2][k]), f3=up2(acc[3][k]);
    float4 stA; stA.x=f0.x; stA.y=f1.x; stA.z=f2.x; stA.w=f3.x;
    float4 stB; stB.x=f0.y; stB.y=f1.y; stB.z=f2.y; stB.w=f3.y;
    *(float4*)&g_cp[base+(size_t)(2*k)*D+c]=stA;
    *(float4*)&g_cp[base+(size_t)(2*k+1)*D+c]=stB;
  }
}

// ---------- oflat = c @ Wv  (cred fused into smem build) ----------
__global__ void k_of(const float* __restrict__ Wv,
                     const float* __restrict__ lng,const float* __restrict__ lnb){
  __shared__ float sc[256*8];
  int t=threadIdx.x, h=blockIdx.x, sp=blockIdx.y, l=blockIdx.z, db=sp*256;
  for(int idx=t;idx<256*8;idx+=128){
    int d=idx>>3, b=idx&7, lb=l*8+b;
    float s=0;
#pragma unroll
    for(int p=0;p<8;p++) s+=g_cp[(size_t)((p*NLB+lb)*NH+h)*D+db+d];
    sc[idx]=lng[l*D+db+d]*(s-g_W0[lb*NH+h])+lnb[l*D+db+d];
  }
  __syncthreads();
  const float* W=Wv+(size_t)l*D*D+(size_t)db*D+h*128+t;
  float acc[NB]={0};
#pragma unroll 8
  for(int d=0;d<256;d++){
    float w=W[(size_t)d*D];
    float4 c0=*(const float4*)&sc[d*8],c1=*(const float4*)&sc[d*8+4];
    FMA8(acc,w,c0,c1);
  }
#pragma unroll
  for(int b=0;b<NB;b++) g_ofp[(size_t)((sp*NL+l)*NB+b)*D+h*128+t]=acc[b];
}

// ---------- attnout = of @ Wo -> hcat partials ----------
__global__ void k_ao(const float* __restrict__ Wo){
  __shared__ float sof[128*8];
  int t=threadIdx.x, cb=blockIdx.x, sp=blockIdx.y, l=blockIdx.z, mb=sp*128, n=cb*256+t;
  for(int idx=t;idx<128*8;idx+=256){
    int m=idx>>3, b=idx&7;
    float s=0;
#pragma unroll
    for(int p=0;p<8;p++) s+=g_ofp[(size_t)((p*NL+l)*NB+b)*D+mb+m];
    sof[idx]=s;
  }
  __syncthreads();
  const float* W=Wo+(size_t)l*D*D+(size_t)mb*D+n;
  float acc[NB]={0};
#pragma unroll 8
  for(int m=0;m<128;m++){
    float w=W[(size_t)m*D];
    float4 o0=*(const float4*)&sof[m*8],o1=*(const float4*)&sof[m*8+4];
    FMA8(acc,w,o0,o1);
  }
#pragma unroll
  for(int b=0;b<NB;b++) g_aop[(size_t)((sp*NL+l)*NB+b)*D+n]=acc[b];
}
__global__ void k_aored(const float* __restrict__ bo){
  int idx=blockIdx.x*256+threadIdx.x; if(idx>=NLB*D) return;
  int n=idx&(D-1), lb=idx>>11, l=lb>>3, b=lb&7;
  float s=0;
#pragma unroll
  for(int sp=0;sp<16;sp++) s+=g_aop[(size_t)sp*NLB*D+idx];
  g_hcat[b*DC+l*D+n]=s+bo[l*D+n];
}

// ---------- MLP layer 1 (f32x2 packed, R10 form) ----------
__global__ void k_m1(const float* __restrict__ W1){
  __shared__ float sh[256*8];
  int t=threadIdx.x, p=blockIdx.x*1024+t*4, cb=blockIdx.y*256;
  for(int idx=t;idx<256*8;idx+=256){ int c=idx>>3,b=idx&7; sh[idx]=g_hcat[b*DC+cb+c]; }
  __syncthreads();
  const float* W=W1+(size_t)cb*IM+p;
  u64 accA[8]={},accB[8]={};
#pragma unroll 8
  for(int c=0;c<256;c++){
    ulonglong2 w2=*(const ulonglong2*)&W[(size_t)c*IM];
    float4 h0=*(const float4*)&sh[c*8], h1=*(const float4*)&sh[c*8+4];
    float hb[8]={h0.x,h0.y,h0.z,h0.w,h1.x,h1.y,h1.z,h1.w};
#pragma unroll
    for(int b=0;b<8;b++){
      u64 hh=pk2(hb[b],hb[b]);
      fma2(accA[b],hh,w2.x); fma2(accB[b],hh,w2.y);
    }
  }
#pragma unroll
  for(int b=0;b<8;b++){
    float2 fa=up2(accA[b]), fb=up2(accB[b]);
    float4 st; st.x=fa.x; st.y=fa.y; st.z=fb.x; st.w=fb.y;
    *(float4*)&g_z1p[(size_t)(blockIdx.y*NB+b)*IM+p]=st;
  }
}
__global__ void k_z1red(const float* __restrict__ b1){
  int idx=blockIdx.x*256+threadIdx.x; if(idx>=NB*IM) return;
  int p=idx&(IM-1);
  float s=b1[p];
#pragma unroll
  for(int sp=0;sp<16;sp++) s+=g_z1p[(size_t)sp*NB*IM+idx];
  g_z1[idx]=0.5f*s*(1.0f+erff(s*0.70710678118654752f));
}

// ---------- MLP layer 2 (f32x2 packed, R10 form) ----------
__global__ void k_m2(const float* __restrict__ W2){
  __shared__ float sz[256*8];
  int t=threadIdx.x, c=blockIdx.x*1024+t*4, pb=blockIdx.y*256;
  for(int idx=t;idx<256*8;idx+=256){ int pp=idx>>3,b=idx&7; sz[idx]=g_z1[b*IM+pb+pp]; }
  __syncthreads();
  const float* W=W2+(size_t)pb*DC+c;
  u64 accA[8]={},accB[8]={};
#pragma unroll 8
  for(int pp=0;pp<256;pp++){
    ulonglong2 w2=*(const ulonglong2*)&W[(size_t)pp*DC];
    float4 z0=*(const float4*)&sz[pp*8], z1v=*(const float4*)&sz[pp*8+4];
    float zb[8]={z0.x,z0.y,z0.z,z0.w,z1v.x,z1v.y,z1v.z,z1v.w};
#pragma unroll
    for(int b=0;b<8;b++){
      u64 zz=pk2(zb[b],zb[b]);
      fma2(accA[b],zz,w2.x); fma2(accB[b],zz,w2.y);
    }
  }
#pragma unroll
  for(int b=0;b<8;b++){
    float2 fa=up2(accA[b]), fb=up2(accB[b]);
    float4 st; st.x=fa.x; st.y=fa.y; st.z=fb.x; st.w=fb.y;
    *(float4*)&g_m2p[(size_t)(blockIdx.y*NB+b)*DC+c]=st;
  }
}
__global__ void k_m2red(const float* __restrict__ b2){
  int idx=blockIdx.x*256+threadIdx.x; if(idx>=NB*DC) return;
  int c=idx&(DC-1);
  float s=b2[c];
#pragma unroll
  for(int sp=0;sp<64;sp++) s+=g_m2p[(size_t)sp*NB*DC+idx];
  g_hfin[idx]=g_hcat[idx]+s;
}

// ---------- final logits ----------
__global__ void k_out(const float* __restrict__ Wl,const float* __restrict__ bl,
                      float* __restrict__ out){
  int b=blockIdx.x, t=threadIdx.x;
  float a0=0,a1=0;
  for(int c=t;c<DC;c+=256){
    float h=g_hfin[b*DC+c];
    a0+=h*Wl[c*2]; a1+=h*Wl[c*2+1];
  }
  __shared__ float s0[256],s1[256];
  s0[t]=a0; s1[t]=a1; __syncthreads();
  for(int o=128;o;o>>=1){ if(t<o){ s0[t]+=s0[t+o]; s1[t]+=s1[t+o]; } __syncthreads(); }
  if(t==0){ out[b*2]=s0[0]+bl[0]; out[b*2+1]=s1[0]+bl[1]; }
}

extern "C" void kernel_launch(void* const* d_in, const int* in_sizes, int n_in,
                              void* d_out, int out_size){
  const float* hs0=(const float*)d_in[0];
  const float* hs1=(const float*)d_in[1];
  const int*   ids=(const int*)d_in[2];
  const float* lng=(const float*)d_in[3];
  const float* lnb=(const float*)d_in[4];
  const float* Wq =(const float*)d_in[5];
  const float* Wk =(const float*)d_in[6];
  const float* Wv =(const float*)d_in[7];
  const float* Wo =(const float*)d_in[8];
  const float* bo =(const float*)d_in[9];
  const float* W1 =(const float*)d_in[10];
  const float* b1 =(const float*)d_in[11];
  const float* W2 =(const float*)d_in[12];
  const float* b2 =(const float*)d_in[13];
  const float* Wl =(const float*)d_in[14];
  const float* bl =(const float*)d_in[15];
  float* out=(float*)d_out;

  k_q<<<dim3(8,16,NL),256>>>(Wq,ids,hs0,hs1,lng,lnb);
  k_qred<<<(NL*NB*D)/256,256>>>();
  k_r<<<dim3(32,16,NL),256>>>(Wk);
  k_pass1<<<dim3(8,8,NLB),256>>>(hs0,hs1,lng);   // 4th launch: profiled
  k_soft<<<dim3(NH,NLB),256>>>(lng,lnb);
  k_pass2<<<dim3(8,2,NLB),256>>>(hs0,hs1);
  k_of<<<dim3(16,8,NL),128>>>(Wv,lng,lnb);
  k_ao<<<dim3(8,16,NL),256>>>(Wo);
  k_aored<<<(NLB*D)/256,256>>>(bo);
  k_m1<<<dim3(IM/1024,16),256>>>(W1);
  k_z1red<<<(NB*IM)/256,256>>>(b1);
  k_m2<<<dim3(DC/1024,64),256>>>(W2);
  k_m2red<<<(NB*DC)/256,256>>>(b2);
  k_out<<<NB,256>>>(Wl,bl,out);
}

// round 13
// speedup vs baseline: 1.1001x; 1.0250x over previous
#include <cuda_runtime.h>
#include <math.h>

#define D 2048
#define SQ 2048
#define NB 8
#define NH 16
#define NL 2
#define DC 4096
#define IM 16384
#define PADID 50257
#define EPSLN 1e-5f
#define NLB (NL*NB)

typedef unsigned long long u64;
__device__ __forceinline__ u64 pk2(float x,float y){u64 r;asm("mov.b64 %0,{%1,%2};":"=l"(r):"f"(x),"f"(y));return r;}
__device__ __forceinline__ void fma2(u64&d,u64 a,u64 b){asm("fma.rn.f32x2 %0,%1,%2,%0;":"+l"(d):"l"(a),"l"(b));}
__device__ __forceinline__ void add2(u64&d,u64 a){asm("add.rn.f32x2 %0,%1,%0;":"+l"(d):"l"(a));}
__device__ __forceinline__ float2 up2(u64 v){float2 r;asm("mov.b64 {%0,%1},%2;":"=f"(r.x),"=f"(r.y):"l"(v));return r;}

__device__ float g_qp[16*NL*NB*D];
__device__ float g_q[NL*NB*D];
__device__ float g_r[NL*NB*D*NH];
__device__ float g_rt[NLB*NH*D];
__device__ float g_dgp[8*NLB*NH*SQ];
__device__ float g_sump[8*NLB*SQ];
__device__ float g_ssqp[8*NLB*SQ];
__device__ float g_wt[NLB*NH*SQ];
__device__ float g_W0[NLB*NH];
__device__ float g_cp[8*NLB*NH*D];
__device__ float g_ofp[8*NLB*D];
__device__ float g_aop[16*NLB*D];
__device__ float g_hcat[NB*DC];
__device__ float g_z1p[16*NB*IM];
__device__ float g_z1[NB*IM];
__device__ float g_m2p[64*NB*DC];
__device__ float g_hfin[NB*DC];

#define FMA8(A,W,Q0,Q1) do{ float _w=(W); \
  A[0]+=Q0.x*_w;A[1]+=Q0.y*_w;A[2]+=Q0.z*_w;A[3]+=Q0.w*_w; \
  A[4]+=Q1.x*_w;A[5]+=Q1.y*_w;A[6]+=Q1.z*_w;A[7]+=Q1.w*_w; }while(0)

// ---------- fused: idx scan + layernorm(last row) + q GEMV partial ----------
__global__ void __launch_bounds__(256) k_q(const float* __restrict__ Wq,
                    const int* __restrict__ ids,
                    const float* __restrict__ hs0,const float* __restrict__ hs1,
                    const float* __restrict__ lng,const float* __restrict__ lnb){
  int t=threadIdx.x, n=blockIdx.x*256+t, sp=blockIdx.y, l=blockIdx.z;
  int w=t>>5, lane=t&31;
  __shared__ float sln[128*NB];
  const float* hs=l?hs1:hs0;
  int best=-1;
  for(int s=lane;s<SQ;s+=32) if(ids[w*SQ+s]!=PADID) best=s;
  for(int o=16;o;o>>=1) best=max(best,__shfl_down_sync(~0u,best,o));
  best=__shfl_sync(~0u,best,0); if(best<0)best=0;
  const float* row=hs+((size_t)w*SQ+best)*D;
  float s1=0.f,s2=0.f;
  for(int i=lane;i<D;i+=32){ float v=row[i]; s1+=v; s2+=v*v; }
  for(int o=16;o;o>>=1){ s1+=__shfl_down_sync(~0u,s1,o); s2+=__shfl_down_sync(~0u,s2,o); }
  s1=__shfl_sync(~0u,s1,0); s2=__shfl_sync(~0u,s2,0);
  float m=s1*(1.f/D), rs=rsqrtf(s2*(1.f/D)-m*m+EPSLN);
  for(int i=lane;i<128;i+=32){
    int gi=sp*128+i;
    sln[i*8+w]=(row[gi]-m)*rs*lng[l*D+gi]+lnb[l*D+gi];
  }
  __syncthreads();
  const float* W=Wq+(size_t)l*D*D+(size_t)sp*128*D+n;
  float acc[NB]={0};
#pragma unroll 8
  for(int i=0;i<128;i++){
    float wv=W[(size_t)i*D];
    float4 l0=*(const float4*)&sln[i*8], l1=*(const float4*)&sln[i*8+4];
    FMA8(acc,wv,l0,l1);
  }
#pragma unroll
  for(int b=0;b<NB;b++) g_qp[(size_t)((sp*NL+l)*NB+b)*D+n]=acc[b];
}
__global__ void k_qred(){
  int idx=blockIdx.x*256+threadIdx.x; if(idx>=NL*NB*D) return;
  float s=0;
#pragma unroll
  for(int sp=0;sp<16;sp++) s+=g_qp[(size_t)sp*NL*NB*D+idx];
  g_q[idx]=s;
}

// ---------- r: tiled smem, no shuffles; writes both layouts ----------
__global__ void __launch_bounds__(256) k_r(const float* __restrict__ Wk){
  __shared__ __align__(16) float wk[64][132];
  __shared__ __align__(16) float qs[8][132];
  int t=threadIdx.x, chunk=blockIdx.x, h=blockIdx.y, l=blockIdx.z;
  int i0=chunk*64;
  for(int idx=t;idx<1024;idx+=256){ int b=idx>>7, d=idx&127; qs[b][d]=g_q[(l*NB+b)*D+h*128+d]; }
  const float* Wp=Wk+(size_t)l*D*D+(size_t)i0*D+h*128;
#pragma unroll
  for(int j=0;j<8;j++){
    int idx=t+j*256; int row=idx>>5, dq=idx&31;
    float4 v=*(const float4*)&Wp[(size_t)row*D+dq*4];
    *(float4*)&wk[row][dq*4]=v;
  }
  __syncthreads();
  int il=t>>3, b=t&7;
  float acc0=0.f, acc1=0.f;
#pragma unroll 8
  for(int dq=0;dq<32;dq++){
    float4 qv=*(const float4*)&qs[b][dq*4];
    float4 w0=*(const float4*)&wk[il][dq*4];
    float4 w1=*(const float4*)&wk[il+32][dq*4];
    acc0+=w0.x*qv.x+w0.y*qv.y+w0.z*qv.z+w0.w*qv.w;
    acc1+=w1.x*qv.x+w1.y*qv.y+w1.z*qv.z+w1.w*qv.w;
  }
  int lb=l*NB+b;
  g_r[((size_t)lb*D+i0+il)*NH+h]=acc0;
  g_r[((size_t)lb*D+i0+il+32)*NH+h]=acc1;
  g_rt[(size_t)(lb*NH+h)*D+i0+il]=acc0;
  g_rt[(size_t)(lb*NH+h)*D+i0+il+32]=acc1;
}

// ---------- pass1: lane-pair rows (coalesced-2x), 4 rows/pair, padded rs ----------
__global__ void __launch_bounds__(256) k_pass1(const float* __restrict__ hs0,const float* __restrict__ hs1,
                        const float* __restrict__ lng){
  __shared__ __align__(16) float rs[256*20];   // 20-float row stride: pair groups 16 banks apart
  int t=threadIdx.x, sp=blockIdx.x, rg=blockIdx.y, lb=blockIdx.z;
  int l=lb>>3, b=lb&7, kb=sp*256;
  const float* x=(l?hs1:hs0)+(size_t)b*SQ*D;
  const float4* rsrc=(const float4*)(g_r+((size_t)lb*D+kb)*NH);
  for(int idx=t;idx<1024;idx+=256){
    int k=idx>>2, m=idx&3;
    float g=lng[l*D+kb+k];
    float4 v=rsrc[idx]; v.x*=g; v.y*=g; v.z*=g; v.w*=g;
    *(float4*)&rs[k*20+m*4]=v;
  }
  __syncthreads();
  int pr=t>>1, half=t&1;
  int r0=rg*512+pr;   // pair owns rows r0, r0+128, r0+256, r0+384
  const float4* xp0=(const float4*)(x+(size_t)(r0      )*D+kb);
  const float4* xp1=(const float4*)(x+(size_t)(r0+128  )*D+kb);
  const float4* xp2=(const float4*)(x+(size_t)(r0+256  )*D+kb);
  const float4* xp3=(const float4*)(x+(size_t)(r0+384  )*D+kb);
  u64 acc[4][8]={}; u64 s01=0,s23=0,q01=0,q23=0;
  for(int kk=0;kk<256;kk+=8){
    int fi=(kk>>2)+half;     // this thread's float4 (half of the 8-k pair-group)
    float4 xa0=xp0[fi], xa1=xp1[fi], xa2=xp2[fi], xa3=xp3[fi];
    int kba=kk+half*4;
#pragma unroll
    for(int e=0;e<4;e++){
      float u0=((const float*)&xa0)[e];
      float u1=((const float*)&xa1)[e];
      float u2=((const float*)&xa2)[e];
      float u3=((const float*)&xa3)[e];
      u64 uv01=pk2(u0,u1), uv23=pk2(u2,u3);
      add2(s01,uv01); fma2(q01,uv01,uv01);
      add2(s23,uv23); fma2(q23,uv23,uv23);
      u64 aa=pk2(u0,u0), bb=pk2(u1,u1), cc=pk2(u2,u2), dd=pk2(u3,u3);
      const ulonglong2* qp=(const ulonglong2*)(rs+(kba+e)*20);
      ulonglong2 qA=qp[0],qB=qp[1],qC=qp[2],qD=qp[3];
      fma2(acc[0][0],aa,qA.x); fma2(acc[0][1],aa,qA.y);
      fma2(acc[0][2],aa,qB.x); fma2(acc[0][3],aa,qB.y);
      fma2(acc[0][4],aa,qC.x); fma2(acc[0][5],aa,qC.y);
      fma2(acc[0][6],aa,qD.x); fma2(acc[0][7],aa,qD.y);
      fma2(acc[1][0],bb,qA.x); fma2(acc[1][1],bb,qA.y);
      fma2(acc[1][2],bb,qB.x); fma2(acc[1][3],bb,qB.y);
      fma2(acc[1][4],bb,qC.x); fma2(acc[1][5],bb,qC.y);
      fma2(acc[1][6],bb,qD.x); fma2(acc[1][7],bb,qD.y);
      fma2(acc[2][0],cc,qA.x); fma2(acc[2][1],cc,qA.y);
      fma2(acc[2][2],cc,qB.x); fma2(acc[2][3],cc,qB.y);
      fma2(acc[2][4],cc,qC.x); fma2(acc[2][5],cc,qC.y);
      fma2(acc[2][6],cc,qD.x); fma2(acc[2][7],cc,qD.y);
      fma2(acc[3][0],dd,qA.x); fma2(acc[3][1],dd,qA.y);
      fma2(acc[3][2],dd,qB.x); fma2(acc[3][3],dd,qB.y);
      fma2(acc[3][4],dd,qC.x); fma2(acc[3][5],dd,qC.y);
      fma2(acc[3][6],dd,qD.x); fma2(acc[3][7],dd,qD.y);
    }
  }
  // pair-combine across halves (lane ^ 1), even lane stores
  size_t base=(size_t)((sp*NLB+lb)*NH)*SQ;
  int spb=(sp*NLB+lb)*SQ;
#pragma unroll
  for(int j=0;j<4;j++){
    int row=r0+j*128;
#pragma unroll
    for(int k=0;k<8;k++){
      float2 f=up2(acc[j][k]);
      float a=f.x+__shfl_xor_sync(0xffffffffu,f.x,1);
      float c=f.y+__shfl_xor_sync(0xffffffffu,f.y,1);
      if(half==0){
        g_dgp[base+(size_t)(2*k)*SQ+row]=a;
        g_dgp[base+(size_t)(2*k+1)*SQ+row]=c;
      }
    }
  }
  {
    float2 fS=up2(s01), fT=up2(s23), fQ=up2(q01), fR=up2(q23);
    float v0=fS.x+__shfl_xor_sync(0xffffffffu,fS.x,1);
    float v1=fS.y+__shfl_xor_sync(0xffffffffu,fS.y,1);
    float v2=fT.x+__shfl_xor_sync(0xffffffffu,fT.x,1);
    float v3=fT.y+__shfl_xor_sync(0xffffffffu,fT.y,1);
    float w0=fQ.x+__shfl_xor_sync(0xffffffffu,fQ.x,1);
    float w1=fQ.y+__shfl_xor_sync(0xffffffffu,fQ.y,1);
    float w2=fR.x+__shfl_xor_sync(0xffffffffu,fR.x,1);
    float w3=fR.y+__shfl_xor_sync(0xffffffffu,fR.y,1);
    if(half==0){
      g_sump[spb+r0]=v0;     g_sump[spb+r0+128]=v1;
      g_sump[spb+r0+256]=v2; g_sump[spb+r0+384]=v3;
      g_ssqp[spb+r0]=w0;     g_ssqp[spb+r0+128]=w1;
      g_ssqp[spb+r0+256]=w2; g_ssqp[spb+r0+384]=w3;
    }
  }
}

// ---------- scores + softmax (t1/t2 inline, coalesced via g_rt) ----------
__global__ void k_soft(const float* __restrict__ lng,const float* __restrict__ lnb){
  int h=blockIdx.x, lb=blockIdx.y, t=threadIdx.x, l=lb>>3;
  __shared__ float sm[256];
  __shared__ float t1s,t2s;
  const float* rt=g_rt+(size_t)(lb*NH+h)*D;
  float p1=0.f,p2=0.f;
#pragma unroll
  for(int k=0;k<8;k++){
    int i=t+k*256;
    float rv=rt[i];
    p1+=lng[l*D+i]*rv; p2+=lnb[l*D+i]*rv;
  }
  sm[t]=p1; __syncthreads();
  for(int o=128;o;o>>=1){ if(t<o) sm[t]+=sm[t+o]; __syncthreads(); }
  if(t==0) t1s=sm[0]; __syncthreads();
  sm[t]=p2; __syncthreads();
  for(int o=128;o;o>>=1){ if(t<o) sm[t]+=sm[t+o]; __syncthreads(); }
  if(t==0) t2s=sm[0]; __syncthreads();
  float t1=t1s, t2=t2s;
  float sc[8],mm[8],rr[8];
#pragma unroll
  for(int k=0;k<8;k++){
    int s=t+k*256; float su=0,sq=0,dg=0;
#pragma unroll
    for(int sp=0;sp<8;sp++){
      su+=g_sump[(sp*NLB+lb)*SQ+s]; sq+=g_ssqp[(sp*NLB+lb)*SQ+s];
      dg+=g_dgp[(size_t)((sp*NLB+lb)*NH+h)*SQ+s];
    }
    float m=su*(1.f/D), var=sq*(1.f/D)-m*m, rsd=rsqrtf(var+EPSLN);
    mm[k]=m; rr[k]=rsd; sc[k]=rsd*(dg-m*t1)+t2;
  }
  float mx=sc[0];
#pragma unroll
  for(int k=1;k<8;k++) mx=fmaxf(mx,sc[k]);
  sm[t]=mx; __syncthreads();
  for(int o=128;o;o>>=1){ if(t<o) sm[t]=fmaxf(sm[t],sm[t+o]); __syncthreads(); }
  mx=sm[0]; __syncthreads();
  float e[8],es=0;
#pragma unroll
  for(int k=0;k<8;k++){ e[k]=expf(sc[k]-mx); es+=e[k]; }
  sm[t]=es; __syncthreads();
  for(int o=128;o;o>>=1){ if(t<o) sm[t]+=sm[t+o]; __syncthreads(); }
  float inv=1.f/sm[0]; __syncthreads();
  float w0=0;
#pragma unroll
  for(int k=0;k<8;k++){
    float wt=e[k]*inv*rr[k];
    g_wt[(size_t)(lb*NH+h)*SQ+t+k*256]=wt; w0+=wt*mm[k];
  }
  sm[t]=w0; __syncthreads();
  for(int o=128;o;o>>=1){ if(t<o) sm[t]+=sm[t+o]; __syncthreads(); }
  if(t==0) g_W0[lb*NH+h]=sm[0];
}

// ---------- pass2: 4 cols/thread (R10 form, coalesced) ----------
__global__ void __launch_bounds__(256) k_pass2(const float* __restrict__ hs0,const float* __restrict__ hs1){
  __shared__ float swt[256*16];
  int t=threadIdx.x, sp=blockIdx.x, cg=blockIdx.y, lb=blockIdx.z;
  int l=lb>>3, b=lb&7, sb=sp*256;
#pragma unroll
  for(int h=0;h<16;h++)
    swt[t*16+h]=g_wt[(size_t)(lb*NH+h)*SQ+sb+t];
  __syncthreads();
  const float* x=(l?hs1:hs0)+(size_t)b*SQ*D;
  int c=cg*1024+t*4;
  u64 acc[4][8]={};
  for(int s=0;s<256;s+=4){
    float4 xv[4];
#pragma unroll
    for(int j=0;j<4;j++) xv[j]=*(const float4*)&x[(size_t)(sb+s+j)*D+c];
#pragma unroll
    for(int j=0;j<4;j++){
      u64 aa=pk2(xv[j].x,xv[j].x), bb=pk2(xv[j].y,xv[j].y);
      u64 cc=pk2(xv[j].z,xv[j].z), dd=pk2(xv[j].w,xv[j].w);
      const ulonglong2* qp=(const ulonglong2*)(swt+(s+j)*16);
      ulonglong2 qA=qp[0],qB=qp[1],qC=qp[2],qD=qp[3];
      fma2(acc[0][0],aa,qA.x); fma2(acc[0][1],aa,qA.y);
      fma2(acc[0][2],aa,qB.x); fma2(acc[0][3],aa,qB.y);
      fma2(acc[0][4],aa,qC.x); fma2(acc[0][5],aa,qC.y);
      fma2(acc[0][6],aa,qD.x); fma2(acc[0][7],aa,qD.y);
      fma2(acc[1][0],bb,qA.x); fma2(acc[1][1],bb,qA.y);
      fma2(acc[1][2],bb,qB.x); fma2(acc[1][3],bb,qB.y);
      fma2(acc[1][4],bb,qC.x); fma2(acc[1][5],bb,qC.y);
      fma2(acc[1][6],bb,qD.x); fma2(acc[1][7],bb,qD.y);
      fma2(acc[2][0],cc,qA.x); fma2(acc[2][1],cc,qA.y);
      fma2(acc[2][2],cc,qB.x); fma2(acc[2][3],cc,qB.y);
      fma2(acc[2][4],cc,qC.x); fma2(acc[2][5],cc,qC.y);
      fma2(acc[2][6],cc,qD.x); fma2(acc[2][7],cc,qD.y);
      fma2(acc[3][0],dd,qA.x); fma2(acc[3][1],dd,qA.y);
      fma2(acc[3][2],dd,qB.x); fma2(acc[3][3],dd,qB.y);
      fma2(acc[3][4],dd,qC.x); fma2(acc[3][5],dd,qC.y);
      fma2(acc[3][6],dd,qD.x); fma2(acc[3][7],dd,qD.y);
    }
  }
  size_t base=(size_t)((sp*NLB+lb)*NH)*D;
#pragma unroll
  for(int k=0;k<8;k++){
    float2 f0=up2(acc[0][k]), f1=up2(acc[1][k]), f2=up2(acc[2][k]), f3=up2(acc[3][k]);
    float4 stA; stA.x=f0.x; stA.y=f1.x; stA.z=f2.x; stA.w=f3.x;
    float4 stB; stB.x=f0.y; stB.y=f1.y; stB.z=f2.y; stB.w=f3.y;
    *(float4*)&g_cp[base+(size_t)(2*k)*D+c]=stA;
    *(float4*)&g_cp[base+(size_t)(2*k+1)*D+c]=stB;
  }
}

// ---------- oflat = c @ Wv  (cred fused into smem build) ----------
__global__ void k_of(const float* __restrict__ Wv,
                     const float* __restrict__ lng,const float* __restrict__ lnb){
  __shared__ float sc[256*8];
  int t=threadIdx.x, h=blockIdx.x, sp=blockIdx.y, l=blockIdx.z, db=sp*256;
  for(int idx=t;idx<256*8;idx+=128){
    int d=idx>>3, b=idx&7, lb=l*8+b;
    float s=0;
#pragma unroll
    for(int p=0;p<8;p++) s+=g_cp[(size_t)((p*NLB+lb)*NH+h)*D+db+d];
    sc[idx]=lng[l*D+db+d]*(s-g_W0[lb*NH+h])+lnb[l*D+db+d];
  }
  __syncthreads();
  const float* W=Wv+(size_t)l*D*D+(size_t)db*D+h*128+t;
  float acc[NB]={0};
#pragma unroll 8
  for(int d=0;d<256;d++){
    float w=W[(size_t)d*D];
    float4 c0=*(const float4*)&sc[d*8],c1=*(const float4*)&sc[d*8+4];
    FMA8(acc,w,c0,c1);
  }
#pragma unroll
  for(int b=0;b<NB;b++) g_ofp[(size_t)((sp*NL+l)*NB+b)*D+h*128+t]=acc[b];
}

// ---------- attnout = of @ Wo -> hcat partials ----------
__global__ void k_ao(const float* __restrict__ Wo){
  __shared__ float sof[128*8];
  int t=threadIdx.x, cb=blockIdx.x, sp=blockIdx.y, l=blockIdx.z, mb=sp*128, n=cb*256+t;
  for(int idx=t;idx<128*8;idx+=256){
    int m=idx>>3, b=idx&7;
    float s=0;
#pragma unroll
    for(int p=0;p<8;p++) s+=g_ofp[(size_t)((p*NL+l)*NB+b)*D+mb+m];
    sof[idx]=s;
  }
  __syncthreads();
  const float* W=Wo+(size_t)l*D*D+(size_t)mb*D+n;
  float acc[NB]={0};
#pragma unroll 8
  for(int m=0;m<128;m++){
    float w=W[(size_t)m*D];
    float4 o0=*(const float4*)&sof[m*8],o1=*(const float4*)&sof[m*8+4];
    FMA8(acc,w,o0,o1);
  }
#pragma unroll
  for(int b=0;b<NB;b++) g_aop[(size_t)((sp*NL+l)*NB+b)*D+n]=acc[b];
}
__global__ void k_aored(const float* __restrict__ bo){
  int idx=blockIdx.x*256+threadIdx.x; if(idx>=NLB*D) return;
  int n=idx&(D-1), lb=idx>>11, l=lb>>3, b=lb&7;
  float s=0;
#pragma unroll
  for(int sp=0;sp<16;sp++) s+=g_aop[(size_t)sp*NLB*D+idx];
  g_hcat[b*DC+l*D+n]=s+bo[l*D+n];
}

// ---------- MLP layer 1 (f32x2 packed) ----------
__global__ void k_m1(const float* __restrict__ W1){
  __shared__ float sh[256*8];
  int t=threadIdx.x, p=blockIdx.x*1024+t*4, cb=blockIdx.y*256;
  for(int idx=t;idx<256*8;idx+=256){ int c=idx>>3,b=idx&7; sh[idx]=g_hcat[b*DC+cb+c]; }
  __syncthreads();
  const float* W=W1+(size_t)cb*IM+p;
  u64 accA[8]={},accB[8]={};
#pragma unroll 8
  for(int c=0;c<256;c++){
    ulonglong2 w2=*(const ulonglong2*)&W[(size_t)c*IM];
    float4 h0=*(const float4*)&sh[c*8], h1=*(const float4*)&sh[c*8+4];
    float hb[8]={h0.x,h0.y,h0.z,h0.w,h1.x,h1.y,h1.z,h1.w};
#pragma unroll
    for(int b=0;b<8;b++){
      u64 hh=pk2(hb[b],hb[b]);
      fma2(accA[b],hh,w2.x); fma2(accB[b],hh,w2.y);
    }
  }
#pragma unroll
  for(int b=0;b<8;b++){
    float2 fa=up2(accA[b]), fb=up2(accB[b]);
    float4 st; st.x=fa.x; st.y=fa.y; st.z=fb.x; st.w=fb.y;
    *(float4*)&g_z1p[(size_t)(blockIdx.y*NB+b)*IM+p]=st;
  }
}
__global__ void k_z1red(const float* __restrict__ b1){
  int idx=blockIdx.x*256+threadIdx.x; if(idx>=NB*IM) return;
  int p=idx&(IM-1);
  float s=b1[p];
#pragma unroll
  for(int sp=0;sp<16;sp++) s+=g_z1p[(size_t)sp*NB*IM+idx];
  g_z1[idx]=0.5f*s*(1.0f+erff(s*0.70710678118654752f));
}

// ---------- MLP layer 2 (f32x2 packed) ----------
__global__ void k_m2(const float* __restrict__ W2){
  __shared__ float sz[256*8];
  int t=threadIdx.x, c=blockIdx.x*1024+t*4, pb=blockIdx.y*256;
  for(int idx=t;idx<256*8;idx+=256){ int pp=idx>>3,b=idx&7; sz[idx]=g_z1[b*IM+pb+pp]; }
  __syncthreads();
  const float* W=W2+(size_t)pb*DC+c;
  u64 accA[8]={},accB[8]={};
#pragma unroll 8
  for(int pp=0;pp<256;pp++){
    ulonglong2 w2=*(const ulonglong2*)&W[(size_t)pp*DC];
    float4 z0=*(const float4*)&sz[pp*8], z1v=*(const float4*)&sz[pp*8+4];
    float zb[8]={z0.x,z0.y,z0.z,z0.w,z1v.x,z1v.y,z1v.z,z1v.w};
#pragma unroll
    for(int b=0;b<8;b++){
      u64 zz=pk2(zb[b],zb[b]);
      fma2(accA[b],zz,w2.x); fma2(accB[b],zz,w2.y);
    }
  }
#pragma unroll
  for(int b=0;b<8;b++){
    float2 fa=up2(accA[b]), fb=up2(accB[b]);
    float4 st; st.x=fa.x; st.y=fa.y; st.z=fb.x; st.w=fb.y;
    *(float4*)&g_m2p[(size_t)(blockIdx.y*NB+b)*DC+c]=st;
  }
}
__global__ void k_m2red(const float* __restrict__ b2){
  int idx=blockIdx.x*256+threadIdx.x; if(idx>=NB*DC) return;
  int c=idx&(DC-1);
  float s=b2[c];
#pragma unroll
  for(int sp=0;sp<64;sp++) s+=g_m2p[(size_t)sp*NB*DC+idx];
  g_hfin[idx]=g_hcat[idx]+s;
}

// ---------- final logits ----------
__global__ void k_out(const float* __restrict__ Wl,const float* __restrict__ bl,
                      float* __restrict__ out){
  int b=blockIdx.x, t=threadIdx.x;
  float a0=0,a1=0;
  for(int c=t;c<DC;c+=256){
    float h=g_hfin[b*DC+c];
    a0+=h*Wl[c*2]; a1+=h*Wl[c*2+1];
  }
  __shared__ float s0[256],s1[256];
  s0[t]=a0; s1[t]=a1; __syncthreads();
  for(int o=128;o;o>>=1){ if(t<o){ s0[t]+=s0[t+o]; s1[t]+=s1[t+o]; } __syncthreads(); }
  if(t==0){ out[b*2]=s0[0]+bl[0]; out[b*2+1]=s1[0]+bl[1]; }
}

extern "C" void kernel_launch(void* const* d_in, const int* in_sizes, int n_in,
                              void* d_out, int out_size){
  const float* hs0=(const float*)d_in[0];
  const float* hs1=(const float*)d_in[1];
  const int*   ids=(const int*)d_in[2];
  const float* lng=(const float*)d_in[3];
  const float* lnb=(const float*)d_in[4];
  const float* Wq =(const float*)d_in[5];
  const float* Wk =(const float*)d_in[6];
  const float* Wv =(const float*)d_in[7];
  const float* Wo =(const float*)d_in[8];
  const float* bo =(const float*)d_in[9];
  const float* W1 =(const float*)d_in[10];
  const float* b1 =(const float*)d_in[11];
  const float* W2 =(const float*)d_in[12];
  const float* b2 =(const float*)d_in[13];
  const float* Wl =(const float*)d_in[14];
  const float* bl =(const float*)d_in[15];
  float* out=(float*)d_out;

  k_q<<<dim3(8,16,NL),256>>>(Wq,ids,hs0,hs1,lng,lnb);
  k_qred<<<(NL*NB*D)/256,256>>>();
  k_r<<<dim3(32,16,NL),256>>>(Wk);
  k_pass1<<<dim3(8,4,NLB),256>>>(hs0,hs1,lng);   // 4th launch: profiled
  k_soft<<<dim3(NH,NLB),256>>>(lng,lnb);
  k_pass2<<<dim3(8,2,NLB),256>>>(hs0,hs1);
  k_of<<<dim3(16,8,NL),128>>>(Wv,lng,lnb);
  k_ao<<<dim3(8,16,NL),256>>>(Wo);
  k_aored<<<(NLB*D)/256,256>>>(bo);
  k_m1<<<dim3(IM/1024,16),256>>>(W1);
  k_z1red<<<(NB*IM)/256,256>>>(b1);
  k_m2<<<dim3(DC/1024,64),256>>>(W2);
  k_m2red<<<(NB*DC)/256,256>>>(b2);
  k_out<<<NB,256>>>(Wl,bl,out);
}

// round 14
// speedup vs baseline: 1.1404x; 1.0367x over previous
#include <cuda_runtime.h>
#include <math.h>

#define D 2048
#define SQ 2048
#define NB 8
#define NH 16
#define NL 2
#define DC 4096
#define IM 16384
#define PADID 50257
#define EPSLN 1e-5f
#define NLB (NL*NB)

typedef unsigned long long u64;
__device__ __forceinline__ u64 pk2(float x,float y){u64 r;asm("mov.b64 %0,{%1,%2};":"=l"(r):"f"(x),"f"(y));return r;}
__device__ __forceinline__ void fma2(u64&d,u64 a,u64 b){asm("fma.rn.f32x2 %0,%1,%2,%0;":"+l"(d):"l"(a),"l"(b));}
__device__ __forceinline__ void add2(u64&d,u64 a){asm("add.rn.f32x2 %0,%1,%0;":"+l"(d):"l"(a));}
__device__ __forceinline__ float2 up2(u64 v){float2 r;asm("mov.b64 {%0,%1},%2;":"=f"(r.x),"=f"(r.y):"l"(v));return r;}

__device__ float g_qp[16*NL*NB*D];
__device__ float g_q[NL*NB*D];
__device__ float g_r[NL*NB*D*NH];
__device__ float g_rt[NLB*NH*D];
__device__ float g_dgp[8*NLB*NH*SQ];
__device__ float g_sump[8*NLB*SQ];
__device__ float g_ssqp[8*NLB*SQ];
__device__ float g_wt[NLB*NH*SQ];
__device__ float g_W0[NLB*NH];
__device__ float g_cp[8*NLB*NH*D];
__device__ float g_ofp[8*NLB*D];
__device__ float g_aop[16*NLB*D];
__device__ float g_hcat[NB*DC];
__device__ float g_z1p[16*NB*IM];
__device__ float g_z1[NB*IM];
__device__ float g_m2p[64*NB*DC];
__device__ float g_hfin[NB*DC];

#define FMA8(A,W,Q0,Q1) do{ float _w=(W); \
  A[0]+=Q0.x*_w;A[1]+=Q0.y*_w;A[2]+=Q0.z*_w;A[3]+=Q0.w*_w; \
  A[4]+=Q1.x*_w;A[5]+=Q1.y*_w;A[6]+=Q1.z*_w;A[7]+=Q1.w*_w; }while(0)

// ---------- fused: idx scan + layernorm(last row) + q GEMV partial ----------
__global__ void __launch_bounds__(256) k_q(const float* __restrict__ Wq,
                    const int* __restrict__ ids,
                    const float* __restrict__ hs0,const float* __restrict__ hs1,
                    const float* __restrict__ lng,const float* __restrict__ lnb){
  int t=threadIdx.x, n=blockIdx.x*256+t, sp=blockIdx.y, l=blockIdx.z;
  int w=t>>5, lane=t&31;
  __shared__ float sln[128*NB];
  const float* hs=l?hs1:hs0;
  int best=-1;
  for(int s=lane;s<SQ;s+=32) if(ids[w*SQ+s]!=PADID) best=s;
  for(int o=16;o;o>>=1) best=max(best,__shfl_down_sync(~0u,best,o));
  best=__shfl_sync(~0u,best,0); if(best<0)best=0;
  const float* row=hs+((size_t)w*SQ+best)*D;
  float s1=0.f,s2=0.f;
  for(int i=lane;i<D;i+=32){ float v=row[i]; s1+=v; s2+=v*v; }
  for(int o=16;o;o>>=1){ s1+=__shfl_down_sync(~0u,s1,o); s2+=__shfl_down_sync(~0u,s2,o); }
  s1=__shfl_sync(~0u,s1,0); s2=__shfl_sync(~0u,s2,0);
  float m=s1*(1.f/D), rs=rsqrtf(s2*(1.f/D)-m*m+EPSLN);
  for(int i=lane;i<128;i+=32){
    int gi=sp*128+i;
    sln[i*8+w]=(row[gi]-m)*rs*lng[l*D+gi]+lnb[l*D+gi];
  }
  __syncthreads();
  const float* W=Wq+(size_t)l*D*D+(size_t)sp*128*D+n;
  float acc[NB]={0};
#pragma unroll 8
  for(int i=0;i<128;i++){
    float wv=W[(size_t)i*D];
    float4 l0=*(const float4*)&sln[i*8], l1=*(const float4*)&sln[i*8+4];
    FMA8(acc,wv,l0,l1);
  }
#pragma unroll
  for(int b=0;b<NB;b++) g_qp[(size_t)((sp*NL+l)*NB+b)*D+n]=acc[b];
}
__global__ void k_qred(){
  int idx=blockIdx.x*256+threadIdx.x; if(idx>=NL*NB*D) return;
  float s=0;
#pragma unroll
  for(int sp=0;sp<16;sp++) s+=g_qp[(size_t)sp*NL*NB*D+idx];
  g_q[idx]=s;
}

// ---------- r: tiled smem, no shuffles; writes both layouts ----------
__global__ void __launch_bounds__(256) k_r(const float* __restrict__ Wk){
  __shared__ __align__(16) float wk[64][132];
  __shared__ __align__(16) float qs[8][132];
  int t=threadIdx.x, chunk=blockIdx.x, h=blockIdx.y, l=blockIdx.z;
  int i0=chunk*64;
  for(int idx=t;idx<1024;idx+=256){ int b=idx>>7, d=idx&127; qs[b][d]=g_q[(l*NB+b)*D+h*128+d]; }
  const float* Wp=Wk+(size_t)l*D*D+(size_t)i0*D+h*128;
#pragma unroll
  for(int j=0;j<8;j++){
    int idx=t+j*256; int row=idx>>5, dq=idx&31;
    float4 v=*(const float4*)&Wp[(size_t)row*D+dq*4];
    *(float4*)&wk[row][dq*4]=v;
  }
  __syncthreads();
  int il=t>>3, b=t&7;
  float acc0=0.f, acc1=0.f;
#pragma unroll 8
  for(int dq=0;dq<32;dq++){
    float4 qv=*(const float4*)&qs[b][dq*4];
    float4 w0=*(const float4*)&wk[il][dq*4];
    float4 w1=*(const float4*)&wk[il+32][dq*4];
    acc0+=w0.x*qv.x+w0.y*qv.y+w0.z*qv.z+w0.w*qv.w;
    acc1+=w1.x*qv.x+w1.y*qv.y+w1.z*qv.z+w1.w*qv.w;
  }
  int lb=l*NB+b;
  g_r[((size_t)lb*D+i0+il)*NH+h]=acc0;
  g_r[((size_t)lb*D+i0+il+32)*NH+h]=acc1;
  g_rt[(size_t)(lb*NH+h)*D+i0+il]=acc0;
  g_rt[(size_t)(lb*NH+h)*D+i0+il+32]=acc1;
}

// ---------- pass1: lane-pair rows, 4 rows/pair, padded rs; forced 2 CTA/SM ----------
__global__ void __launch_bounds__(256,2) k_pass1(const float* __restrict__ hs0,const float* __restrict__ hs1,
                        const float* __restrict__ lng){
  __shared__ __align__(16) float rs[256*20];   // 20-float row stride: pair groups 16 banks apart
  int t=threadIdx.x, sp=blockIdx.x, rg=blockIdx.y, lb=blockIdx.z;
  int l=lb>>3, b=lb&7, kb=sp*256;
  const float* x=(l?hs1:hs0)+(size_t)b*SQ*D;
  const float4* rsrc=(const float4*)(g_r+((size_t)lb*D+kb)*NH);
  for(int idx=t;idx<1024;idx+=256){
    int k=idx>>2, m=idx&3;
    float g=lng[l*D+kb+k];
    float4 v=rsrc[idx]; v.x*=g; v.y*=g; v.z*=g; v.w*=g;
    *(float4*)&rs[k*20+m*4]=v;
  }
  __syncthreads();
  int pr=t>>1, half=t&1;
  int r0=rg*512+pr;   // pair owns rows r0, r0+128, r0+256, r0+384
  const float4* xp0=(const float4*)(x+(size_t)(r0      )*D+kb);
  const float4* xp1=(const float4*)(x+(size_t)(r0+128  )*D+kb);
  const float4* xp2=(const float4*)(x+(size_t)(r0+256  )*D+kb);
  const float4* xp3=(const float4*)(x+(size_t)(r0+384  )*D+kb);
  u64 acc[4][8]={}; u64 s01=0,s23=0,q01=0,q23=0;
  for(int kk=0;kk<256;kk+=8){
    int fi=(kk>>2)+half;     // this thread's float4 (half of the 8-k pair-group)
    float4 xa0=xp0[fi], xa1=xp1[fi], xa2=xp2[fi], xa3=xp3[fi];
    int kba=kk+half*4;
#pragma unroll
    for(int e=0;e<4;e++){
      float u0=((const float*)&xa0)[e];
      float u1=((const float*)&xa1)[e];
      float u2=((const float*)&xa2)[e];
      float u3=((const float*)&xa3)[e];
      u64 uv01=pk2(u0,u1), uv23=pk2(u2,u3);
      add2(s01,uv01); fma2(q01,uv01,uv01);
      add2(s23,uv23); fma2(q23,uv23,uv23);
      u64 aa=pk2(u0,u0), bb=pk2(u1,u1), cc=pk2(u2,u2), dd=pk2(u3,u3);
      const ulonglong2* qp=(const ulonglong2*)(rs+(kba+e)*20);
      ulonglong2 qA=qp[0],qB=qp[1],qC=qp[2],qD=qp[3];
      fma2(acc[0][0],aa,qA.x); fma2(acc[0][1],aa,qA.y);
      fma2(acc[0][2],aa,qB.x); fma2(acc[0][3],aa,qB.y);
      fma2(acc[0][4],aa,qC.x); fma2(acc[0][5],aa,qC.y);
      fma2(acc[0][6],aa,qD.x); fma2(acc[0][7],aa,qD.y);
      fma2(acc[1][0],bb,qA.x); fma2(acc[1][1],bb,qA.y);
      fma2(acc[1][2],bb,qB.x); fma2(acc[1][3],bb,qB.y);
      fma2(acc[1][4],bb,qC.x); fma2(acc[1][5],bb,qC.y);
      fma2(acc[1][6],bb,qD.x); fma2(acc[1][7],bb,qD.y);
      fma2(acc[2][0],cc,qA.x); fma2(acc[2][1],cc,qA.y);
      fma2(acc[2][2],cc,qB.x); fma2(acc[2][3],cc,qB.y);
      fma2(acc[2][4],cc,qC.x); fma2(acc[2][5],cc,qC.y);
      fma2(acc[2][6],cc,qD.x); fma2(acc[2][7],cc,qD.y);
      fma2(acc[3][0],dd,qA.x); fma2(acc[3][1],dd,qA.y);
      fma2(acc[3][2],dd,qB.x); fma2(acc[3][3],dd,qB.y);
      fma2(acc[3][4],dd,qC.x); fma2(acc[3][5],dd,qC.y);
      fma2(acc[3][6],dd,qD.x); fma2(acc[3][7],dd,qD.y);
    }
  }
  // pair-combine across halves (lane ^ 1), even lane stores
  size_t base=(size_t)((sp*NLB+lb)*NH)*SQ;
  int spb=(sp*NLB+lb)*SQ;
#pragma unroll
  for(int j=0;j<4;j++){
    int row=r0+j*128;
#pragma unroll
    for(int k=0;k<8;k++){
      float2 f=up2(acc[j][k]);
      float a=f.x+__shfl_xor_sync(0xffffffffu,f.x,1);
      float c=f.y+__shfl_xor_sync(0xffffffffu,f.y,1);
      if(half==0){
        g_dgp[base+(size_t)(2*k)*SQ+row]=a;
        g_dgp[base+(size_t)(2*k+1)*SQ+row]=c;
      }
    }
  }
  {
    float2 fS=up2(s01), fT=up2(s23), fQ=up2(q01), fR=up2(q23);
    float v0=fS.x+__shfl_xor_sync(0xffffffffu,fS.x,1);
    float v1=fS.y+__shfl_xor_sync(0xffffffffu,fS.y,1);
    float v2=fT.x+__shfl_xor_sync(0xffffffffu,fT.x,1);
    float v3=fT.y+__shfl_xor_sync(0xffffffffu,fT.y,1);
    float w0=fQ.x+__shfl_xor_sync(0xffffffffu,fQ.x,1);
    float w1=fQ.y+__shfl_xor_sync(0xffffffffu,fQ.y,1);
    float w2=fR.x+__shfl_xor_sync(0xffffffffu,fR.x,1);
    float w3=fR.y+__shfl_xor_sync(0xffffffffu,fR.y,1);
    if(half==0){
      g_sump[spb+r0]=v0;     g_sump[spb+r0+128]=v1;
      g_sump[spb+r0+256]=v2; g_sump[spb+r0+384]=v3;
      g_ssqp[spb+r0]=w0;     g_ssqp[spb+r0+128]=w1;
      g_ssqp[spb+r0+256]=w2; g_ssqp[spb+r0+384]=w3;
    }
  }
}

// ---------- scores + softmax (t1/t2 inline, coalesced via g_rt) ----------
__global__ void k_soft(const float* __restrict__ lng,const float* __restrict__ lnb){
  int h=blockIdx.x, lb=blockIdx.y, t=threadIdx.x, l=lb>>3;
  __shared__ float sm[256];
  __shared__ float t1s,t2s;
  const float* rt=g_rt+(size_t)(lb*NH+h)*D;
  float p1=0.f,p2=0.f;
#pragma unroll
  for(int k=0;k<8;k++){
    int i=t+k*256;
    float rv=rt[i];
    p1+=lng[l*D+i]*rv; p2+=lnb[l*D+i]*rv;
  }
  sm[t]=p1; __syncthreads();
  for(int o=128;o;o>>=1){ if(t<o) sm[t]+=sm[t+o]; __syncthreads(); }
  if(t==0) t1s=sm[0]; __syncthreads();
  sm[t]=p2; __syncthreads();
  for(int o=128;o;o>>=1){ if(t<o) sm[t]+=sm[t+o]; __syncthreads(); }
  if(t==0) t2s=sm[0]; __syncthreads();
  float t1=t1s, t2=t2s;
  float sc[8],mm[8],rr[8];
#pragma unroll
  for(int k=0;k<8;k++){
    int s=t+k*256; float su=0,sq=0,dg=0;
#pragma unroll
    for(int sp=0;sp<8;sp++){
      su+=g_sump[(sp*NLB+lb)*SQ+s]; sq+=g_ssqp[(sp*NLB+lb)*SQ+s];
      dg+=g_dgp[(size_t)((sp*NLB+lb)*NH+h)*SQ+s];
    }
    float m=su*(1.f/D), var=sq*(1.f/D)-m*m, rsd=rsqrtf(var+EPSLN);
    mm[k]=m; rr[k]=rsd; sc[k]=rsd*(dg-m*t1)+t2;
  }
  float mx=sc[0];
#pragma unroll
  for(int k=1;k<8;k++) mx=fmaxf(mx,sc[k]);
  sm[t]=mx; __syncthreads();
  for(int o=128;o;o>>=1){ if(t<o) sm[t]=fmaxf(sm[t],sm[t+o]); __syncthreads(); }
  mx=sm[0]; __syncthreads();
  float e[8],es=0;
#pragma unroll
  for(int k=0;k<8;k++){ e[k]=expf(sc[k]-mx); es+=e[k]; }
  sm[t]=es; __syncthreads();
  for(int o=128;o;o>>=1){ if(t<o) sm[t]+=sm[t+o]; __syncthreads(); }
  float inv=1.f/sm[0]; __syncthreads();
  float w0=0;
#pragma unroll
  for(int k=0;k<8;k++){
    float wt=e[k]*inv*rr[k];
    g_wt[(size_t)(lb*NH+h)*SQ+t+k*256]=wt; w0+=wt*mm[k];
  }
  sm[t]=w0; __syncthreads();
  for(int o=128;o;o>>=1){ if(t<o) sm[t]+=sm[t+o]; __syncthreads(); }
  if(t==0) g_W0[lb*NH+h]=sm[0];
}

// ---------- pass2: 4 cols/thread (R10 form, coalesced) ----------
__global__ void __launch_bounds__(256) k_pass2(const float* __restrict__ hs0,const float* __restrict__ hs1){
  __shared__ float swt[256*16];
  int t=threadIdx.x, sp=blockIdx.x, cg=blockIdx.y, lb=blockIdx.z;
  int l=lb>>3, b=lb&7, sb=sp*256;
#pragma unroll
  for(int h=0;h<16;h++)
    swt[t*16+h]=g_wt[(size_t)(lb*NH+h)*SQ+sb+t];
  __syncthreads();
  const float* x=(l?hs1:hs0)+(size_t)b*SQ*D;
  int c=cg*1024+t*4;
  u64 acc[4][8]={};
  for(int s=0;s<256;s+=4){
    float4 xv[4];
#pragma unroll
    for(int j=0;j<4;j++) xv[j]=*(const float4*)&x[(size_t)(sb+s+j)*D+c];
#pragma unroll
    for(int j=0;j<4;j++){
      u64 aa=pk2(xv[j].x,xv[j].x), bb=pk2(xv[j].y,xv[j].y);
      u64 cc=pk2(xv[j].z,xv[j].z), dd=pk2(xv[j].w,xv[j].w);
      const ulonglong2* qp=(const ulonglong2*)(swt+(s+j)*16);
      ulonglong2 qA=qp[0],qB=qp[1],qC=qp[2],qD=qp[3];
      fma2(acc[0][0],aa,qA.x); fma2(acc[0][1],aa,qA.y);
      fma2(acc[0][2],aa,qB.x); fma2(acc[0][3],aa,qB.y);
      fma2(acc[0][4],aa,qC.x); fma2(acc[0][5],aa,qC.y);
      fma2(acc[0][6],aa,qD.x); fma2(acc[0][7],aa,qD.y);
      fma2(acc[1][0],bb,qA.x); fma2(acc[1][1],bb,qA.y);
      fma2(acc[1][2],bb,qB.x); fma2(acc[1][3],bb,qB.y);
      fma2(acc[1][4],bb,qC.x); fma2(acc[1][5],bb,qC.y);
      fma2(acc[1][6],bb,qD.x); fma2(acc[1][7],bb,qD.y);
      fma2(acc[2][0],cc,qA.x); fma2(acc[2][1],cc,qA.y);
      fma2(acc[2][2],cc,qB.x); fma2(acc[2][3],cc,qB.y);
      fma2(acc[2][4],cc,qC.x); fma2(acc[2][5],cc,qC.y);
      fma2(acc[2][6],cc,qD.x); fma2(acc[2][7],cc,qD.y);
      fma2(acc[3][0],dd,qA.x); fma2(acc[3][1],dd,qA.y);
      fma2(acc[3][2],dd,qB.x); fma2(acc[3][3],dd,qB.y);
      fma2(acc[3][4],dd,qC.x); fma2(acc[3][5],dd,qC.y);
      fma2(acc[3][6],dd,qD.x); fma2(acc[3][7],dd,qD.y);
    }
  }
  size_t base=(size_t)((sp*NLB+lb)*NH)*D;
#pragma unroll
  for(int k=0;k<8;k++){
    float2 f0=up2(acc[0][k]), f1=up2(acc[1][k]), f2=up2(acc[2][k]), f3=up2(acc[3][k]);
    float4 stA; stA.x=f0.x; stA.y=f1.x; stA.z=f2.x; stA.w=f3.x;
    float4 stB; stB.x=f0.y; stB.y=f1.y; stB.z=f2.y; stB.w=f3.y;
    *(float4*)&g_cp[base+(size_t)(2*k)*D+c]=stA;
    *(float4*)&g_cp[base+(size_t)(2*k+1)*D+c]=stB;
  }
}

// ---------- oflat = c @ Wv  (cred fused into smem build) ----------
__global__ void k_of(const float* __restrict__ Wv,
                     const float* __restrict__ lng,const float* __restrict__ lnb){
  __shared__ float sc[256*8];
  int t=threadIdx.x, h=blockIdx.x, sp=blockIdx.y, l=blockIdx.z, db=sp*256;
  for(int idx=t;idx<256*8;idx+=128){
    int d=idx>>3, b=idx&7, lb=l*8+b;
    float s=0;
#pragma unroll
    for(int p=0;p<8;p++) s+=g_cp[(size_t)((p*NLB+lb)*NH+h)*D+db+d];
    sc[idx]=lng[l*D+db+d]*(s-g_W0[lb*NH+h])+lnb[l*D+db+d];
  }
  __syncthreads();
  const float* W=Wv+(size_t)l*D*D+(size_t)db*D+h*128+t;
  float acc[NB]={0};
#pragma unroll 8
  for(int d=0;d<256;d++){
    float w=W[(size_t)d*D];
    float4 c0=*(const float4*)&sc[d*8],c1=*(const float4*)&sc[d*8+4];
    FMA8(acc,w,c0,c1);
  }
#pragma unroll
  for(int b=0;b<NB;b++) g_ofp[(size_t)((sp*NL+l)*NB+b)*D+h*128+t]=acc[b];
}

// ---------- attnout = of @ Wo -> hcat partials ----------
__global__ void k_ao(const float* __restrict__ Wo){
  __shared__ float sof[128*8];
  int t=threadIdx.x, cb=blockIdx.x, sp=blockIdx.y, l=blockIdx.z, mb=sp*128, n=cb*256+t;
  for(int idx=t;idx<128*8;idx+=256){
    int m=idx>>3, b=idx&7;
    float s=0;
#pragma unroll
    for(int p=0;p<8;p++) s+=g_ofp[(size_t)((p*NL+l)*NB+b)*D+mb+m];
    sof[idx]=s;
  }
  __syncthreads();
  const float* W=Wo+(size_t)l*D*D+(size_t)mb*D+n;
  float acc[NB]={0};
#pragma unroll 8
  for(int m=0;m<128;m++){
    float w=W[(size_t)m*D];
    float4 o0=*(const float4*)&sof[m*8],o1=*(const float4*)&sof[m*8+4];
    FMA8(acc,w,o0,o1);
  }
#pragma unroll
  for(int b=0;b<NB;b++) g_aop[(size_t)((sp*NL+l)*NB+b)*D+n]=acc[b];
}
__global__ void k_aored(const float* __restrict__ bo){
  int idx=blockIdx.x*256+threadIdx.x; if(idx>=NLB*D) return;
  int n=idx&(D-1), lb=idx>>11, l=lb>>3, b=lb&7;
  float s=0;
#pragma unroll
  for(int sp=0;sp<16;sp++) s+=g_aop[(size_t)sp*NLB*D+idx];
  g_hcat[b*DC+l*D+n]=s+bo[l*D+n];
}

// ---------- MLP layer 1 (f32x2 packed) ----------
__global__ void k_m1(const float* __restrict__ W1){
  __shared__ float sh[256*8];
  int t=threadIdx.x, p=blockIdx.x*1024+t*4, cb=blockIdx.y*256;
  for(int idx=t;idx<256*8;idx+=256){ int c=idx>>3,b=idx&7; sh[idx]=g_hcat[b*DC+cb+c]; }
  __syncthreads();
  const float* W=W1+(size_t)cb*IM+p;
  u64 accA[8]={},accB[8]={};
#pragma unroll 8
  for(int c=0;c<256;c++){
    ulonglong2 w2=*(const ulonglong2*)&W[(size_t)c*IM];
    float4 h0=*(const float4*)&sh[c*8], h1=*(const float4*)&sh[c*8+4];
    float hb[8]={h0.x,h0.y,h0.z,h0.w,h1.x,h1.y,h1.z,h1.w};
#pragma unroll
    for(int b=0;b<8;b++){
      u64 hh=pk2(hb[b],hb[b]);
      fma2(accA[b],hh,w2.x); fma2(accB[b],hh,w2.y);
    }
  }
#pragma unroll
  for(int b=0;b<8;b++){
    float2 fa=up2(accA[b]), fb=up2(accB[b]);
    float4 st; st.x=fa.x; st.y=fa.y; st.z=fb.x; st.w=fb.y;
    *(float4*)&g_z1p[(size_t)(blockIdx.y*NB+b)*IM+p]=st;
  }
}
__global__ void k_z1red(const float* __restrict__ b1){
  int idx=blockIdx.x*256+threadIdx.x; if(idx>=NB*IM) return;
  int p=idx&(IM-1);
  float s=b1[p];
#pragma unroll
  for(int sp=0;sp<16;sp++) s+=g_z1p[(size_t)sp*NB*IM+idx];
  g_z1[idx]=0.5f*s*(1.0f+erff(s*0.70710678118654752f));
}

// ---------- MLP layer 2 (f32x2 packed) ----------
__global__ void k_m2(const float* __restrict__ W2){
  __shared__ float sz[256*8];
  int t=threadIdx.x, c=blockIdx.x*1024+t*4, pb=blockIdx.y*256;
  for(int idx=t;idx<256*8;idx+=256){ int pp=idx>>3,b=idx&7; sz[idx]=g_z1[b*IM+pb+pp]; }
  __syncthreads();
  const float* W=W2+(size_t)pb*DC+c;
  u64 accA[8]={},accB[8]={};
#pragma unroll 8
  for(int pp=0;pp<256;pp++){
    ulonglong2 w2=*(const ulonglong2*)&W[(size_t)pp*DC];
    float4 z0=*(const float4*)&sz[pp*8], z1v=*(const float4*)&sz[pp*8+4];
    float zb[8]={z0.x,z0.y,z0.z,z0.w,z1v.x,z1v.y,z1v.z,z1v.w};
#pragma unroll
    for(int b=0;b<8;b++){
      u64 zz=pk2(zb[b],zb[b]);
      fma2(accA[b],zz,w2.x); fma2(accB[b],zz,w2.y);
    }
  }
#pragma unroll
  for(int b=0;b<8;b++){
    float2 fa=up2(accA[b]), fb=up2(accB[b]);
    float4 st; st.x=fa.x; st.y=fa.y; st.z=fb.x; st.w=fb.y;
    *(float4*)&g_m2p[(size_t)(blockIdx.y*NB+b)*DC+c]=st;
  }
}
__global__ void k_m2red(const float* __restrict__ b2){
  int idx=blockIdx.x*256+threadIdx.x; if(idx>=NB*DC) return;
  int c=idx&(DC-1);
  float s=b2[c];
#pragma unroll
  for(int sp=0;sp<64;sp++) s+=g_m2p[(size_t)sp*NB*DC+idx];
  g_hfin[idx]=g_hcat[idx]+s;
}

// ---------- final logits ----------
__global__ void k_out(const float* __restrict__ Wl,const float* __restrict__ bl,
                      float* __restrict__ out){
  int b=blockIdx.x, t=threadIdx.x;
  float a0=0,a1=0;
  for(int c=t;c<DC;c+=256){
    float h=g_hfin[b*DC+c];
    a0+=h*Wl[c*2]; a1+=h*Wl[c*2+1];
  }
  __shared__ float s0[256],s1[256];
  s0[t]=a0; s1[t]=a1; __syncthreads();
  for(int o=128;o;o>>=1){ if(t<o){ s0[t]+=s0[t+o]; s1[t]+=s1[t+o]; } __syncthreads(); }
  if(t==0){ out[b*2]=s0[0]+bl[0]; out[b*2+1]=s1[0]+bl[1]; }
}

extern "C" void kernel_launch(void* const* d_in, const int* in_sizes, int n_in,
                              void* d_out, int out_size){
  const float* hs0=(const float*)d_in[0];
  const float* hs1=(const float*)d_in[1];
  const int*   ids=(const int*)d_in[2];
  const float* lng=(const float*)d_in[3];
  const float* lnb=(const float*)d_in[4];
  const float* Wq =(const float*)d_in[5];
  const float* Wk =(const float*)d_in[6];
  const float* Wv =(const float*)d_in[7];
  const float* Wo =(const float*)d_in[8];
  const float* bo =(const float*)d_in[9];
  const float* W1 =(const float*)d_in[10];
  const float* b1 =(const float*)d_in[11];
  const float* W2 =(const float*)d_in[12];
  const float* b2 =(const float*)d_in[13];
  const float* Wl =(const float*)d_in[14];
  const float* bl =(const float*)d_in[15];
  float* out=(float*)d_out;

  k_q<<<dim3(8,16,NL),256>>>(Wq,ids,hs0,hs1,lng,lnb);
  k_qred<<<(NL*NB*D)/256,256>>>();
  k_r<<<dim3(32,16,NL),256>>>(Wk);
  k_pass1<<<dim3(8,4,NLB),256>>>(hs0,hs1,lng);   // 4th launch: profiled
  k_soft<<<dim3(NH,NLB),256>>>(lng,lnb);
  k_pass2<<<dim3(8,2,NLB),256>>>(hs0,hs1);
  k_of<<<dim3(16,8,NL),128>>>(Wv,lng,lnb);
  k_ao<<<dim3(8,16,NL),256>>>(Wo);
  k_aored<<<(NLB*D)/256,256>>>(bo);
  k_m1<<<dim3(IM/1024,16),256>>>(W1);
  k_z1red<<<(NB*IM)/256,256>>>(b1);
  k_m2<<<dim3(DC/1024,64),256>>>(W2);
  k_m2red<<<(NB*DC)/256,256>>>(b2);
  k_out<<<NB,256>>>(Wl,bl,out);
}

// round 15
// speedup vs baseline: 1.2224x; 1.0719x over previous
#include <cuda_runtime.h>
#include <math.h>

#define D 2048
#define SQ 2048
#define NB 8
#define NH 16
#define NL 2
#define DC 4096
#define IM 16384
#define PADID 50257
#define EPSLN 1e-5f
#define NLB (NL*NB)

typedef unsigned long long u64;
__device__ __forceinline__ u64 pk2(float x,float y){u64 r;asm("mov.b64 %0,{%1,%2};":"=l"(r):"f"(x),"f"(y));return r;}
__device__ __forceinline__ void fma2(u64&d,u64 a,u64 b){asm("fma.rn.f32x2 %0,%1,%2,%0;":"+l"(d):"l"(a),"l"(b));}
__device__ __forceinline__ void add2(u64&d,u64 a){asm("add.rn.f32x2 %0,%1,%0;":"+l"(d):"l"(a));}
__device__ __forceinline__ float2 up2(u64 v){float2 r;asm("mov.b64 {%0,%1},%2;":"=f"(r.x),"=f"(r.y):"l"(v));return r;}

__device__ float g_qp[16*NL*NB*D];
__device__ float g_q[NL*NB*D];
__device__ float g_r[NL*NB*D*NH];
__device__ float g_rt[NLB*NH*D];
__device__ float g_dgp[8*NLB*NH*SQ];
__device__ float g_sump[8*NLB*SQ];
__device__ float g_ssqp[8*NLB*SQ];
__device__ float g_wt[NLB*NH*SQ];
__device__ float g_W0[NLB*NH];
__device__ float g_cp[8*NLB*NH*D];
__device__ float g_ofp[8*NLB*D];
__device__ float g_aop[16*NLB*D];
__device__ float g_hcat[NB*DC];
__device__ float g_z1p[16*NB*IM];
__device__ float g_z1[NB*IM];
__device__ float g_m2p[64*NB*DC];
__device__ float g_hfin[NB*DC];

#define FMA8(A,W,Q0,Q1) do{ float _w=(W); \
  A[0]+=Q0.x*_w;A[1]+=Q0.y*_w;A[2]+=Q0.z*_w;A[3]+=Q0.w*_w; \
  A[4]+=Q1.x*_w;A[5]+=Q1.y*_w;A[6]+=Q1.z*_w;A[7]+=Q1.w*_w; }while(0)

// ---------- fused: idx scan + layernorm(last row) + q GEMV partial ----------
__global__ void __launch_bounds__(256) k_q(const float* __restrict__ Wq,
                    const int* __restrict__ ids,
                    const float* __restrict__ hs0,const float* __restrict__ hs1,
                    const float* __restrict__ lng,const float* __restrict__ lnb){
  int t=threadIdx.x, n=blockIdx.x*256+t, sp=blockIdx.y, l=blockIdx.z;
  int w=t>>5, lane=t&31;
  __shared__ float sln[128*NB];
  const float* hs=l?hs1:hs0;
  int best=-1;
  for(int s=lane;s<SQ;s+=32) if(ids[w*SQ+s]!=PADID) best=s;
  for(int o=16;o;o>>=1) best=max(best,__shfl_down_sync(~0u,best,o));
  best=__shfl_sync(~0u,best,0); if(best<0)best=0;
  const float* row=hs+((size_t)w*SQ+best)*D;
  float s1=0.f,s2=0.f;
  for(int i=lane;i<D;i+=32){ float v=row[i]; s1+=v; s2+=v*v; }
  for(int o=16;o;o>>=1){ s1+=__shfl_down_sync(~0u,s1,o); s2+=__shfl_down_sync(~0u,s2,o); }
  s1=__shfl_sync(~0u,s1,0); s2=__shfl_sync(~0u,s2,0);
  float m=s1*(1.f/D), rs=rsqrtf(s2*(1.f/D)-m*m+EPSLN);
  for(int i=lane;i<128;i+=32){
    int gi=sp*128+i;
    sln[i*8+w]=(row[gi]-m)*rs*lng[l*D+gi]+lnb[l*D+gi];
  }
  __syncthreads();
  const float* W=Wq+(size_t)l*D*D+(size_t)sp*128*D+n;
  float acc[NB]={0};
#pragma unroll 8
  for(int i=0;i<128;i++){
    float wv=W[(size_t)i*D];
    float4 l0=*(const float4*)&sln[i*8], l1=*(const float4*)&sln[i*8+4];
    FMA8(acc,wv,l0,l1);
  }
#pragma unroll
  for(int b=0;b<NB;b++) g_qp[(size_t)((sp*NL+l)*NB+b)*D+n]=acc[b];
}
__global__ void k_qred(){
  int idx=blockIdx.x*256+threadIdx.x; if(idx>=NL*NB*D) return;
  float s=0;
#pragma unroll
  for(int sp=0;sp<16;sp++) s+=g_qp[(size_t)sp*NL*NB*D+idx];
  g_q[idx]=s;
}

// ---------- r: tiled smem, no shuffles; writes both layouts ----------
__global__ void __launch_bounds__(256) k_r(const float* __restrict__ Wk){
  __shared__ __align__(16) float wk[64][132];
  __shared__ __align__(16) float qs[8][132];
  int t=threadIdx.x, chunk=blockIdx.x, h=blockIdx.y, l=blockIdx.z;
  int i0=chunk*64;
  for(int idx=t;idx<1024;idx+=256){ int b=idx>>7, d=idx&127; qs[b][d]=g_q[(l*NB+b)*D+h*128+d]; }
  const float* Wp=Wk+(size_t)l*D*D+(size_t)i0*D+h*128;
#pragma unroll
  for(int j=0;j<8;j++){
    int idx=t+j*256; int row=idx>>5, dq=idx&31;
    float4 v=*(const float4*)&Wp[(size_t)row*D+dq*4];
    *(float4*)&wk[row][dq*4]=v;
  }
  __syncthreads();
  int il=t>>3, b=t&7;
  float acc0=0.f, acc1=0.f;
#pragma unroll 8
  for(int dq=0;dq<32;dq++){
    float4 qv=*(const float4*)&qs[b][dq*4];
    float4 w0=*(const float4*)&wk[il][dq*4];
    float4 w1=*(const float4*)&wk[il+32][dq*4];
    acc0+=w0.x*qv.x+w0.y*qv.y+w0.z*qv.z+w0.w*qv.w;
    acc1+=w1.x*qv.x+w1.y*qv.y+w1.z*qv.z+w1.w*qv.w;
  }
  int lb=l*NB+b;
  g_r[((size_t)lb*D+i0+il)*NH+h]=acc0;
  g_r[((size_t)lb*D+i0+il+32)*NH+h]=acc1;
  g_rt[(size_t)(lb*NH+h)*D+i0+il]=acc0;
  g_rt[(size_t)(lb*NH+h)*D+i0+il+32]=acc1;
}

// ---------- pass1: lane-pair rows, 4 rows/pair, padded rs; forced 2 CTA/SM ----------
__global__ void __launch_bounds__(256,2) k_pass1(const float* __restrict__ hs0,const float* __restrict__ hs1,
                        const float* __restrict__ lng){
  __shared__ __align__(16) float rs[256*20];   // 20-float row stride: pair groups 16 banks apart
  int t=threadIdx.x, sp=blockIdx.x, rg=blockIdx.y, lb=blockIdx.z;
  int l=lb>>3, b=lb&7, kb=sp*256;
  const float* x=(l?hs1:hs0)+(size_t)b*SQ*D;
  const float4* rsrc=(const float4*)(g_r+((size_t)lb*D+kb)*NH);
  for(int idx=t;idx<1024;idx+=256){
    int k=idx>>2, m=idx&3;
    float g=lng[l*D+kb+k];
    float4 v=rsrc[idx]; v.x*=g; v.y*=g; v.z*=g; v.w*=g;
    *(float4*)&rs[k*20+m*4]=v;
  }
  __syncthreads();
  int pr=t>>1, half=t&1;
  int r0=rg*512+pr;   // pair owns rows r0, r0+128, r0+256, r0+384
  const float4* xp0=(const float4*)(x+(size_t)(r0      )*D+kb);
  const float4* xp1=(const float4*)(x+(size_t)(r0+128  )*D+kb);
  const float4* xp2=(const float4*)(x+(size_t)(r0+256  )*D+kb);
  const float4* xp3=(const float4*)(x+(size_t)(r0+384  )*D+kb);
  u64 acc[4][8]={}; u64 s01=0,s23=0,q01=0,q23=0;
  for(int kk=0;kk<256;kk+=8){
    int fi=(kk>>2)+half;     // this thread's float4 (half of the 8-k pair-group)
    float4 xa0=xp0[fi], xa1=xp1[fi], xa2=xp2[fi], xa3=xp3[fi];
    int kba=kk+half*4;
#pragma unroll
    for(int e=0;e<4;e++){
      float u0=((const float*)&xa0)[e];
      float u1=((const float*)&xa1)[e];
      float u2=((const float*)&xa2)[e];
      float u3=((const float*)&xa3)[e];
      u64 uv01=pk2(u0,u1), uv23=pk2(u2,u3);
      add2(s01,uv01); fma2(q01,uv01,uv01);
      add2(s23,uv23); fma2(q23,uv23,uv23);
      u64 aa=pk2(u0,u0), bb=pk2(u1,u1), cc=pk2(u2,u2), dd=pk2(u3,u3);
      const ulonglong2* qp=(const ulonglong2*)(rs+(kba+e)*20);
      ulonglong2 qA=qp[0],qB=qp[1],qC=qp[2],qD=qp[3];
      fma2(acc[0][0],aa,qA.x); fma2(acc[0][1],aa,qA.y);
      fma2(acc[0][2],aa,qB.x); fma2(acc[0][3],aa,qB.y);
      fma2(acc[0][4],aa,qC.x); fma2(acc[0][5],aa,qC.y);
      fma2(acc[0][6],aa,qD.x); fma2(acc[0][7],aa,qD.y);
      fma2(acc[1][0],bb,qA.x); fma2(acc[1][1],bb,qA.y);
      fma2(acc[1][2],bb,qB.x); fma2(acc[1][3],bb,qB.y);
      fma2(acc[1][4],bb,qC.x); fma2(acc[1][5],bb,qC.y);
      fma2(acc[1][6],bb,qD.x); fma2(acc[1][7],bb,qD.y);
      fma2(acc[2][0],cc,qA.x); fma2(acc[2][1],cc,qA.y);
      fma2(acc[2][2],cc,qB.x); fma2(acc[2][3],cc,qB.y);
      fma2(acc[2][4],cc,qC.x); fma2(acc[2][5],cc,qC.y);
      fma2(acc[2][6],cc,qD.x); fma2(acc[2][7],cc,qD.y);
      fma2(acc[3][0],dd,qA.x); fma2(acc[3][1],dd,qA.y);
      fma2(acc[3][2],dd,qB.x); fma2(acc[3][3],dd,qB.y);
      fma2(acc[3][4],dd,qC.x); fma2(acc[3][5],dd,qC.y);
      fma2(acc[3][6],dd,qD.x); fma2(acc[3][7],dd,qD.y);
    }
  }
  // pair-combine across halves (lane ^ 1), even lane stores
  size_t base=(size_t)((sp*NLB+lb)*NH)*SQ;
  int spb=(sp*NLB+lb)*SQ;
#pragma unroll
  for(int j=0;j<4;j++){
    int row=r0+j*128;
#pragma unroll
    for(int k=0;k<8;k++){
      float2 f=up2(acc[j][k]);
      float a=f.x+__shfl_xor_sync(0xffffffffu,f.x,1);
      float c=f.y+__shfl_xor_sync(0xffffffffu,f.y,1);
      if(half==0){
        g_dgp[base+(size_t)(2*k)*SQ+row]=a;
        g_dgp[base+(size_t)(2*k+1)*SQ+row]=c;
      }
    }
  }
  {
    float2 fS=up2(s01), fT=up2(s23), fQ=up2(q01), fR=up2(q23);
    float v0=fS.x+__shfl_xor_sync(0xffffffffu,fS.x,1);
    float v1=fS.y+__shfl_xor_sync(0xffffffffu,fS.y,1);
    float v2=fT.x+__shfl_xor_sync(0xffffffffu,fT.x,1);
    float v3=fT.y+__shfl_xor_sync(0xffffffffu,fT.y,1);
    float w0=fQ.x+__shfl_xor_sync(0xffffffffu,fQ.x,1);
    float w1=fQ.y+__shfl_xor_sync(0xffffffffu,fQ.y,1);
    float w2=fR.x+__shfl_xor_sync(0xffffffffu,fR.x,1);
    float w3=fR.y+__shfl_xor_sync(0xffffffffu,fR.y,1);
    if(half==0){
      g_sump[spb+r0]=v0;     g_sump[spb+r0+128]=v1;
      g_sump[spb+r0+256]=v2; g_sump[spb+r0+384]=v3;
      g_ssqp[spb+r0]=w0;     g_ssqp[spb+r0+128]=w1;
      g_ssqp[spb+r0+256]=w2; g_ssqp[spb+r0+384]=w3;
    }
  }
}

// ---------- scores + softmax (t1/t2 inline, coalesced via g_rt) ----------
__global__ void k_soft(const float* __restrict__ lng,const float* __restrict__ lnb){
  int h=blockIdx.x, lb=blockIdx.y, t=threadIdx.x, l=lb>>3;
  __shared__ float sm[256];
  __shared__ float t1s,t2s;
  const float* rt=g_rt+(size_t)(lb*NH+h)*D;
  float p1=0.f,p2=0.f;
#pragma unroll
  for(int k=0;k<8;k++){
    int i=t+k*256;
    float rv=rt[i];
    p1+=lng[l*D+i]*rv; p2+=lnb[l*D+i]*rv;
  }
  sm[t]=p1; __syncthreads();
  for(int o=128;o;o>>=1){ if(t<o) sm[t]+=sm[t+o]; __syncthreads(); }
  if(t==0) t1s=sm[0]; __syncthreads();
  sm[t]=p2; __syncthreads();
  for(int o=128;o;o>>=1){ if(t<o) sm[t]+=sm[t+o]; __syncthreads(); }
  if(t==0) t2s=sm[0]; __syncthreads();
  float t1=t1s, t2=t2s;
  float sc[8],mm[8],rr[8];
#pragma unroll
  for(int k=0;k<8;k++){
    int s=t+k*256; float su=0,sq=0,dg=0;
#pragma unroll
    for(int sp=0;sp<8;sp++){
      su+=g_sump[(sp*NLB+lb)*SQ+s]; sq+=g_ssqp[(sp*NLB+lb)*SQ+s];
      dg+=g_dgp[(size_t)((sp*NLB+lb)*NH+h)*SQ+s];
    }
    float m=su*(1.f/D), var=sq*(1.f/D)-m*m, rsd=rsqrtf(var+EPSLN);
    mm[k]=m; rr[k]=rsd; sc[k]=rsd*(dg-m*t1)+t2;
  }
  float mx=sc[0];
#pragma unroll
  for(int k=1;k<8;k++) mx=fmaxf(mx,sc[k]);
  sm[t]=mx; __syncthreads();
  for(int o=128;o;o>>=1){ if(t<o) sm[t]=fmaxf(sm[t],sm[t+o]); __syncthreads(); }
  mx=sm[0]; __syncthreads();
  float e[8],es=0;
#pragma unroll
  for(int k=0;k<8;k++){ e[k]=expf(sc[k]-mx); es+=e[k]; }
  sm[t]=es; __syncthreads();
  for(int o=128;o;o>>=1){ if(t<o) sm[t]+=sm[t+o]; __syncthreads(); }
  float inv=1.f/sm[0]; __syncthreads();
  float w0=0;
#pragma unroll
  for(int k=0;k<8;k++){
    float wt=e[k]*inv*rr[k];
    g_wt[(size_t)(lb*NH+h)*SQ+t+k*256]=wt; w0+=wt*mm[k];
  }
  sm[t]=w0; __syncthreads();
  for(int o=128;o;o>>=1){ if(t<o) sm[t]+=sm[t+o]; __syncthreads(); }
  if(t==0) g_W0[lb*NH+h]=sm[0];
}

// ---------- pass2: 4 cols/thread, forced 2 CTA/SM ----------
__global__ void __launch_bounds__(256,2) k_pass2(const float* __restrict__ hs0,const float* __restrict__ hs1){
  __shared__ float swt[256*16];
  int t=threadIdx.x, sp=blockIdx.x, cg=blockIdx.y, lb=blockIdx.z;
  int l=lb>>3, b=lb&7, sb=sp*256;
#pragma unroll
  for(int h=0;h<16;h++)
    swt[t*16+h]=g_wt[(size_t)(lb*NH+h)*SQ+sb+t];
  __syncthreads();
  const float* x=(l?hs1:hs0)+(size_t)b*SQ*D;
  int c=cg*1024+t*4;
  u64 acc[4][8]={};
  for(int s=0;s<256;s+=4){
    float4 xv[4];
#pragma unroll
    for(int j=0;j<4;j++) xv[j]=*(const float4*)&x[(size_t)(sb+s+j)*D+c];
#pragma unroll
    for(int j=0;j<4;j++){
      u64 aa=pk2(xv[j].x,xv[j].x), bb=pk2(xv[j].y,xv[j].y);
      u64 cc=pk2(xv[j].z,xv[j].z), dd=pk2(xv[j].w,xv[j].w);
      const ulonglong2* qp=(const ulonglong2*)(swt+(s+j)*16);
      ulonglong2 qA=qp[0],qB=qp[1],qC=qp[2],qD=qp[3];
      fma2(acc[0][0],aa,qA.x); fma2(acc[0][1],aa,qA.y);
      fma2(acc[0][2],aa,qB.x); fma2(acc[0][3],aa,qB.y);
      fma2(acc[0][4],aa,qC.x); fma2(acc[0][5],aa,qC.y);
      fma2(acc[0][6],aa,qD.x); fma2(acc[0][7],aa,qD.y);
      fma2(acc[1][0],bb,qA.x); fma2(acc[1][1],bb,qA.y);
      fma2(acc[1][2],bb,qB.x); fma2(acc[1][3],bb,qB.y);
      fma2(acc[1][4],bb,qC.x); fma2(acc[1][5],bb,qC.y);
      fma2(acc[1][6],bb,qD.x); fma2(acc[1][7],bb,qD.y);
      fma2(acc[2][0],cc,qA.x); fma2(acc[2][1],cc,qA.y);
      fma2(acc[2][2],cc,qB.x); fma2(acc[2][3],cc,qB.y);
      fma2(acc[2][4],cc,qC.x); fma2(acc[2][5],cc,qC.y);
      fma2(acc[2][6],cc,qD.x); fma2(acc[2][7],cc,qD.y);
      fma2(acc[3][0],dd,qA.x); fma2(acc[3][1],dd,qA.y);
      fma2(acc[3][2],dd,qB.x); fma2(acc[3][3],dd,qB.y);
      fma2(acc[3][4],dd,qC.x); fma2(acc[3][5],dd,qC.y);
      fma2(acc[3][6],dd,qD.x); fma2(acc[3][7],dd,qD.y);
    }
  }
  size_t base=(size_t)((sp*NLB+lb)*NH)*D;
#pragma unroll
  for(int k=0;k<8;k++){
    float2 f0=up2(acc[0][k]), f1=up2(acc[1][k]), f2=up2(acc[2][k]), f3=up2(acc[3][k]);
    float4 stA; stA.x=f0.x; stA.y=f1.x; stA.z=f2.x; stA.w=f3.x;
    float4 stB; stB.x=f0.y; stB.y=f1.y; stB.z=f2.y; stB.w=f3.y;
    *(float4*)&g_cp[base+(size_t)(2*k)*D+c]=stA;
    *(float4*)&g_cp[base+(size_t)(2*k+1)*D+c]=stB;
  }
}

// ---------- oflat = c @ Wv  (cred fused into smem build) ----------
__global__ void k_of(const float* __restrict__ Wv,
                     const float* __restrict__ lng,const float* __restrict__ lnb){
  __shared__ float sc[256*8];
  int t=threadIdx.x, h=blockIdx.x, sp=blockIdx.y, l=blockIdx.z, db=sp*256;
  for(int idx=t;idx<256*8;idx+=128){
    int d=idx>>3, b=idx&7, lb=l*8+b;
    float s=0;
#pragma unroll
    for(int p=0;p<8;p++) s+=g_cp[(size_t)((p*NLB+lb)*NH+h)*D+db+d];
    sc[idx]=lng[l*D+db+d]*(s-g_W0[lb*NH+h])+lnb[l*D+db+d];
  }
  __syncthreads();
  const float* W=Wv+(size_t)l*D*D+(size_t)db*D+h*128+t;
  float acc[NB]={0};
#pragma unroll 8
  for(int d=0;d<256;d++){
    float w=W[(size_t)d*D];
    float4 c0=*(const float4*)&sc[d*8],c1=*(const float4*)&sc[d*8+4];
    FMA8(acc,w,c0,c1);
  }
#pragma unroll
  for(int b=0;b<NB;b++) g_ofp[(size_t)((sp*NL+l)*NB+b)*D+h*128+t]=acc[b];
}

// ---------- attnout = of @ Wo -> hcat partials ----------
__global__ void k_ao(const float* __restrict__ Wo){
  __shared__ float sof[128*8];
  int t=threadIdx.x, cb=blockIdx.x, sp=blockIdx.y, l=blockIdx.z, mb=sp*128, n=cb*256+t;
  for(int idx=t;idx<128*8;idx+=256){
    int m=idx>>3, b=idx&7;
    float s=0;
#pragma unroll
    for(int p=0;p<8;p++) s+=g_ofp[(size_t)((p*NL+l)*NB+b)*D+mb+m];
    sof[idx]=s;
  }
  __syncthreads();
  const float* W=Wo+(size_t)l*D*D+(size_t)mb*D+n;
  float acc[NB]={0};
#pragma unroll 8
  for(int m=0;m<128;m++){
    float w=W[(size_t)m*D];
    float4 o0=*(const float4*)&sof[m*8],o1=*(const float4*)&sof[m*8+4];
    FMA8(acc,w,o0,o1);
  }
#pragma unroll
  for(int b=0;b<NB;b++) g_aop[(size_t)((sp*NL+l)*NB+b)*D+n]=acc[b];
}
__global__ void k_aored(const float* __restrict__ bo){
  int idx=blockIdx.x*256+threadIdx.x; if(idx>=NLB*D) return;
  int n=idx&(D-1), lb=idx>>11, l=lb>>3, b=lb&7;
  float s=0;
#pragma unroll
  for(int sp=0;sp<16;sp++) s+=g_aop[(size_t)sp*NLB*D+idx];
  g_hcat[b*DC+l*D+n]=s+bo[l*D+n];
}

// ---------- MLP layer 1 (f32x2 packed, forced 2 CTA/SM) ----------
__global__ void __launch_bounds__(256,2) k_m1(const float* __restrict__ W1){
  __shared__ float sh[256*8];
  int t=threadIdx.x, p=blockIdx.x*1024+t*4, cb=blockIdx.y*256;
  for(int idx=t;idx<256*8;idx+=256){ int c=idx>>3,b=idx&7; sh[idx]=g_hcat[b*DC+cb+c]; }
  __syncthreads();
  const float* W=W1+(size_t)cb*IM+p;
  u64 accA[8]={},accB[8]={};
#pragma unroll 8
  for(int c=0;c<256;c++){
    ulonglong2 w2=*(const ulonglong2*)&W[(size_t)c*IM];
    float4 h0=*(const float4*)&sh[c*8], h1=*(const float4*)&sh[c*8+4];
    float hb[8]={h0.x,h0.y,h0.z,h0.w,h1.x,h1.y,h1.z,h1.w};
#pragma unroll
    for(int b=0;b<8;b++){
      u64 hh=pk2(hb[b],hb[b]);
      fma2(accA[b],hh,w2.x); fma2(accB[b],hh,w2.y);
    }
  }
#pragma unroll
  for(int b=0;b<8;b++){
    float2 fa=up2(accA[b]), fb=up2(accB[b]);
    float4 st; st.x=fa.x; st.y=fa.y; st.z=fb.x; st.w=fb.y;
    *(float4*)&g_z1p[(size_t)(blockIdx.y*NB+b)*IM+p]=st;
  }
}
__global__ void k_z1red(const float* __restrict__ b1){
  int idx=blockIdx.x*256+threadIdx.x; if(idx>=NB*IM) return;
  int p=idx&(IM-1);
  float s=b1[p];
#pragma unroll
  for(int sp=0;sp<16;sp++) s+=g_z1p[(size_t)sp*NB*IM+idx];
  g_z1[idx]=0.5f*s*(1.0f+erff(s*0.70710678118654752f));
}

// ---------- MLP layer 2 (f32x2 packed, forced 2 CTA/SM) ----------
__global__ void __launch_bounds__(256,2) k_m2(const float* __restrict__ W2){
  __shared__ float sz[256*8];
  int t=threadIdx.x, c=blockIdx.x*1024+t*4, pb=blockIdx.y*256;
  for(int idx=t;idx<256*8;idx+=256){ int pp=idx>>3,b=idx&7; sz[idx]=g_z1[b*IM+pb+pp]; }
  __syncthreads();
  const float* W=W2+(size_t)pb*DC+c;
  u64 accA[8]={},accB[8]={};
#pragma unroll 8
  for(int pp=0;pp<256;pp++){
    ulonglong2 w2=*(const ulonglong2*)&W[(size_t)pp*DC];
    float4 z0=*(const float4*)&sz[pp*8], z1v=*(const float4*)&sz[pp*8+4];
    float zb[8]={z0.x,z0.y,z0.z,z0.w,z1v.x,z1v.y,z1v.z,z1v.w};
#pragma unroll
    for(int b=0;b<8;b++){
      u64 zz=pk2(zb[b],zb[b]);
      fma2(accA[b],zz,w2.x); fma2(accB[b],zz,w2.y);
    }
  }
#pragma unroll
  for(int b=0;b<8;b++){
    float2 fa=up2(accA[b]), fb=up2(accB[b]);
    float4 st; st.x=fa.x; st.y=fa.y; st.z=fb.x; st.w=fb.y;
    *(float4*)&g_m2p[(size_t)(blockIdx.y*NB+b)*DC+c]=st;
  }
}
__global__ void k_m2red(const float* __restrict__ b2){
  int idx=blockIdx.x*256+threadIdx.x; if(idx>=NB*DC) return;
  int c=idx&(DC-1);
  float s=b2[c];
#pragma unroll
  for(int sp=0;sp<64;sp++) s+=g_m2p[(size_t)sp*NB*DC+idx];
  g_hfin[idx]=g_hcat[idx]+s;
}

// ---------- final logits ----------
__global__ void k_out(const float* __restrict__ Wl,const float* __restrict__ bl,
                      float* __restrict__ out){
  int b=blockIdx.x, t=threadIdx.x;
  float a0=0,a1=0;
  for(int c=t;c<DC;c+=256){
    float h=g_hfin[b*DC+c];
    a0+=h*Wl[c*2]; a1+=h*Wl[c*2+1];
  }
  __shared__ float s0[256],s1[256];
  s0[t]=a0; s1[t]=a1; __syncthreads();
  for(int o=128;o;o>>=1){ if(t<o){ s0[t]+=s0[t+o]; s1[t]+=s1[t+o]; } __syncthreads(); }
  if(t==0){ out[b*2]=s0[0]+bl[0]; out[b*2+1]=s1[0]+bl[1]; }
}

extern "C" void kernel_launch(void* const* d_in, const int* in_sizes, int n_in,
                              void* d_out, int out_size){
  const float* hs0=(const float*)d_in[0];
  const float* hs1=(const float*)d_in[1];
  const int*   ids=(const int*)d_in[2];
  const float* lng=(const float*)d_in[3];
  const float* lnb=(const float*)d_in[4];
  const float* Wq =(const float*)d_in[5];
  const float* Wk =(const float*)d_in[6];
  const float* Wv =(const float*)d_in[7];
  const float* Wo =(const float*)d_in[8];
  const float* bo =(const float*)d_in[9];
  const float* W1 =(const float*)d_in[10];
  const float* b1 =(const float*)d_in[11];
  const float* W2 =(const float*)d_in[12];
  const float* b2 =(const float*)d_in[13];
  const float* Wl =(const float*)d_in[14];
  const float* bl =(const float*)d_in[15];
  float* out=(float*)d_out;

  k_q<<<dim3(8,16,NL),256>>>(Wq,ids,hs0,hs1,lng,lnb);
  k_qred<<<(NL*NB*D)/256,256>>>();
  k_r<<<dim3(32,16,NL),256>>>(Wk);
  k_pass1<<<dim3(8,4,NLB),256>>>(hs0,hs1,lng);   // 4th launch: profiled
  k_soft<<<dim3(NH,NLB),256>>>(lng,lnb);
  k_pass2<<<dim3(8,2,NLB),256>>>(hs0,hs1);
  k_of<<<dim3(16,8,NL),128>>>(Wv,lng,lnb);
  k_ao<<<dim3(8,16,NL),256>>>(Wo);
  k_aored<<<(NLB*D)/256,256>>>(bo);
  k_m1<<<dim3(IM/1024,16),256>>>(W1);
  k_z1red<<<(NB*IM)/256,256>>>(b1);
  k_m2<<<dim3(DC/1024,64),256>>>(W2);
  k_m2red<<<(NB*DC)/256,256>>>(b2);
  k_out<<<NB,256>>>(Wl,bl,out);
}